// round 4
// baseline (speedup 1.0000x reference)
#include <cuda_runtime.h>
#include <cuda_fp16.h>
#include <cstdint>

#define NB   16
#define CIN  512
#define COUT 512
#define RES  64

// ---------------- device scratch ----------------
__device__ float  g_styles[NB * CIN];
__device__ float  g_s[NB * CIN];
__device__ float  g_rn[COUT];
__device__ float  g_qraw[COUT * CIN];
__device__ float  g_d[NB * COUT];
__device__ __half g_wth[9 * COUT * CIN];            // [kk][oc][i] fp16
__device__ __half g_xph[NB * 68 * 68 * CIN];        // NHWC padded, style-scaled fp16
__device__ __half g_y0h[NB * COUT * 66 * 66];       // conv out (+d, +bias) fp16

// ---------------- helpers ----------------
__device__ __forceinline__ uint32_t smem_u32(const void* p) {
    uint32_t a;
    asm("{ .reg .u64 t; cvta.to.shared.u64 t, %1; cvt.u32.u64 %0, t; }" : "=r"(a) : "l"(p));
    return a;
}
__device__ __forceinline__ uint32_t swz(uint32_t o) { return o ^ ((o >> 3) & 0x70); }

__device__ __forceinline__ void ldsm4(uint32_t* r, uint32_t addr) {
    asm volatile("ldmatrix.sync.aligned.m8n8.x4.shared.b16 {%0,%1,%2,%3}, [%4];"
        : "=r"(r[0]), "=r"(r[1]), "=r"(r[2]), "=r"(r[3]) : "r"(addr));
}
__device__ __forceinline__ void mma16816(float* c, const uint32_t* a, uint32_t b0, uint32_t b1) {
    asm volatile("mma.sync.aligned.m16n8k16.row.col.f32.f16.f16.f32 "
        "{%0,%1,%2,%3}, {%4,%5,%6,%7}, {%8,%9}, {%0,%1,%2,%3};"
        : "+f"(c[0]), "+f"(c[1]), "+f"(c[2]), "+f"(c[3])
        : "r"(a[0]), "r"(a[1]), "r"(a[2]), "r"(a[3]), "r"(b0), "r"(b1));
}

// ---------------- K1: styles ----------------
__global__ void k_styles(const float* __restrict__ w,
                         const float* __restrict__ aw,
                         const float* __restrict__ ab) {
    int n = blockIdx.x, tid = threadIdx.x;
    __shared__ float wsh[512];
    wsh[tid] = w[n * 512 + tid];
    __syncthreads();
    int warp = tid >> 5, lane = tid & 31;
    for (int i = warp; i < 512; i += 16) {
        float acc = 0.f;
        const float* row = aw + (size_t)i * 512;
        for (int j = lane; j < 512; j += 32) acc += wsh[j] * row[j];
        #pragma unroll
        for (int off = 16; off; off >>= 1) acc += __shfl_down_sync(0xffffffffu, acc, off);
        if (lane == 0) g_styles[n * 512 + i] = acc * 0.04419417382415922f + ab[i];
    }
}

// ---------------- K2: s normalize ----------------
__global__ void k_snorm() {
    int tid = threadIdx.x;
    __shared__ float red[256];
    __shared__ float rstd_s;
    float a = 0.f;
    for (int idx = tid; idx < NB * CIN; idx += 256) { float v = g_styles[idx]; a += v * v; }
    red[tid] = a; __syncthreads();
    for (int off = 128; off; off >>= 1) { if (tid < off) red[tid] += red[tid + off]; __syncthreads(); }
    if (tid == 0) rstd_s = rsqrtf(red[0] / (float)(NB * CIN));
    __syncthreads();
    float rs = rstd_s;
    for (int idx = tid; idx < NB * CIN; idx += 256) g_s[idx] = g_styles[idx] * rs;
}

// ---------------- K3: rn, qraw, wth[kk][oc][i] fp16 ----------------
__global__ void k_rn(const float* __restrict__ cw) {
    int o = blockIdx.x, tid = threadIdx.x;
    const float* cwo = cw + (size_t)o * 4608;
    __shared__ float red[256];
    __shared__ float rn_s;
    float a = 0.f;
    for (int idx = tid; idx < 4608; idx += 256) { float v = cwo[idx]; a += v * v; }
    red[tid] = a; __syncthreads();
    for (int off = 128; off; off >>= 1) { if (tid < off) red[tid] += red[tid + off]; __syncthreads(); }
    if (tid == 0) { rn_s = rsqrtf(red[0] / 4608.f); g_rn[o] = rn_s; }
    __syncthreads();
    float rn = rn_s;
    for (int i = tid; i < 512; i += 256) {
        float q = 0.f;
        #pragma unroll
        for (int kk = 0; kk < 9; kk++) { float v = cwo[i * 9 + kk]; q += v * v; }
        g_qraw[o * 512 + i] = q;
    }
    #pragma unroll
    for (int kk = 0; kk < 9; kk++)
        for (int i = tid; i < 512; i += 256)
            g_wth[((size_t)(kk * 512) + o) * 512 + i] = __float2half(cwo[i * 9 + kk] * rn);
}

// ---------------- K4: d[n][o]  (grid 512, block 128) ----------------
__global__ void k_d() {
    int o = blockIdx.x, tid = threadIdx.x;
    int warp = tid >> 5, lane = tid & 31;
    __shared__ float qsh[512];
    for (int i = tid; i < 512; i += 128) qsh[i] = g_qraw[o * 512 + i];
    __syncthreads();
    float rn = g_rn[o];
    for (int n = warp; n < NB; n += 4) {
        float acc = 0.f;
        for (int i = lane; i < 512; i += 32) {
            float sv = g_s[n * 512 + i];
            acc += sv * sv * qsh[i];
        }
        #pragma unroll
        for (int off = 16; off; off >>= 1) acc += __shfl_down_sync(0xffffffffu, acc, off);
        if (lane == 0) g_d[n * 512 + o] = rsqrtf(rn * rn * acc + 1e-8f);
    }
}

// ---------------- K5: NHWC padded, scaled input fp16 ----------------
__global__ __launch_bounds__(512) void k_pad(const float* __restrict__ x) {
    int yy = blockIdx.x, n = blockIdx.y, tid = threadIdx.x;
    __shared__ float ts[128][65];
    __half* orow = g_xph + ((size_t)(n * 68 + yy) * 68) * 512;
    bool inner = (yy >= 2 && yy < 66);
    for (int ct = 0; ct < 4; ct++) {
        __syncthreads();
        if (inner) {
            #pragma unroll
            for (int it = 0; it < 16; it++) {
                int idx = it * 512 + tid;
                int c = idx >> 6, xx = idx & 63;
                int cg = ct * 128 + c;
                ts[c][xx] = x[(((size_t)(n * 512) + cg) * 64 + (yy - 2)) * 64 + xx] * g_s[n * 512 + cg];
            }
        }
        __syncthreads();
        #pragma unroll
        for (int it = 0; it < 17; it++) {
            int idx = it * 512 + tid;
            if (idx < 68 * 128) {
                int xx = idx >> 7, c = idx & 127;
                float v = 0.f;
                if (inner && xx >= 2 && xx < 66) v = ts[c][xx - 2];
                orow[xx * 512 + ct * 128 + c] = __float2half(v);
            }
        }
    }
}

// ---------------- K6: conv via mma.sync fp16 implicit GEMM ----------------
#define STAGE_B 49152
__global__ __launch_bounds__(256, 1) void k_conv(const float* __restrict__ cbias) {
    extern __shared__ char smem[];
    uint32_t sb = smem_u32(smem);
    int tid = threadIdx.x, lane = tid & 31, wid = tid >> 5;
    int pt = blockIdx.x, ot = blockIdx.y, n = blockIdx.z;
    int p0 = pt * 256;
    int wm = wid & 1, wn = wid >> 1;

    float C[4][8][4];
    #pragma unroll
    for (int i = 0; i < 4; i++)
        #pragma unroll
        for (int j = 0; j < 8; j++)
            #pragma unroll
            for (int k = 0; k < 4; k++) C[i][j][k] = 0.f;

    int ch = tid & 7;
    int trow = tid >> 3;

    uint32_t browoff[8];
    #pragma unroll
    for (int b = 0; b < 8; b++) {
        int row = b * 32 + trow;
        int p = p0 + row; if (p > 4355) p = 4355;
        int y = p / 66, xx = p - y * 66;
        browoff[b] = ((uint32_t)(n * 68 + y) * 68 + xx) * 512;
    }
    uint32_t sA_st[4], sB_st[8];
    #pragma unroll
    for (int a = 0; a < 4; a++) sA_st[a] = swz(((a * 32 + trow) * 128) + ch * 16);
    #pragma unroll
    for (int b = 0; b < 8; b++) sB_st[b] = 16384 + swz(((b * 32 + trow) * 128) + ch * 16);

#define LOAD_TILE(js_, slot_) do { \
    int kk_ = (js_) >> 3; int i0_ = ((js_) & 7) << 6; \
    int ky_ = kk_ / 3, kx_ = kk_ - ky_ * 3; \
    uint32_t stb_ = sb + (uint32_t)(slot_) * STAGE_B; \
    const __half* ap_ = g_wth + ((size_t)(kk_ * 512 + ot * 128)) * 512 + i0_ + ch * 8; \
    _Pragma("unroll") \
    for (int a_ = 0; a_ < 4; a_++) { \
        uint32_t sa_ = stb_ + sA_st[a_]; \
        const __half* ga_ = ap_ + (size_t)(a_ * 32 + trow) * 512; \
        asm volatile("cp.async.cg.shared.global [%0], [%1], 16;" :: "r"(sa_), "l"(ga_)); \
    } \
    uint32_t koff_ = (uint32_t)(ky_ * 68 + kx_) * 512 + i0_ + ch * 8; \
    _Pragma("unroll") \
    for (int b_ = 0; b_ < 8; b_++) { \
        uint32_t sa_ = stb_ + sB_st[b_]; \
        const __half* gb_ = g_xph + browoff[b_] + koff_; \
        asm volatile("cp.async.cg.shared.global [%0], [%1], 16;" :: "r"(sa_), "l"(gb_)); \
    } \
    asm volatile("cp.async.commit_group;" ::: "memory"); \
} while (0)

    LOAD_TILE(0, 0);
    LOAD_TILE(1, 1);

    uint32_t aRow = wm * 64 + (lane & 15);
    uint32_t aCol = (uint32_t)(lane >> 4);
    uint32_t bRow = wn * 64 + ((lane >> 4) << 3) + (lane & 7);
    uint32_t bCol = (uint32_t)((lane >> 3) & 1);

    for (int js = 0; js < 72; js++) {
        int cur = js % 3;
        asm volatile("cp.async.wait_group 1;" ::: "memory");
        __syncthreads();
        if (js + 2 < 72) { LOAD_TILE(js + 2, (js + 2) % 3); }
        else { asm volatile("cp.async.commit_group;" ::: "memory"); }

        uint32_t sA = sb + (uint32_t)cur * STAGE_B;
        uint32_t sB = sA + 16384;
        #pragma unroll
        for (int ks = 0; ks < 4; ks++) {
            uint32_t af[4][4], bf[4][4];
            #pragma unroll
            for (int mt = 0; mt < 4; mt++)
                ldsm4(af[mt], sA + swz((aRow + mt * 16) * 128 + (ks * 2 + aCol) * 16));
            #pragma unroll
            for (int bt = 0; bt < 4; bt++)
                ldsm4(bf[bt], sB + swz((bRow + bt * 16) * 128 + (ks * 2 + bCol) * 16));
            #pragma unroll
            for (int mt = 0; mt < 4; mt++)
                #pragma unroll
                for (int bt = 0; bt < 4; bt++) {
                    mma16816(C[mt][2 * bt],     af[mt], bf[bt][0], bf[bt][1]);
                    mma16816(C[mt][2 * bt + 1], af[mt], bf[bt][2], bf[bt][3]);
                }
        }
    }

    // ---- epilogue: *d + bias -> g_y0h (fp16) ----
    int obase = ot * 128 + wm * 64;
    __half* y0n = g_y0h + (size_t)n * 512 * 4356;
    #pragma unroll
    for (int mt = 0; mt < 4; mt++) {
        int r0 = obase + mt * 16 + (lane >> 2);
        int r1 = r0 + 8;
        float d0 = g_d[n * 512 + r0], bb0 = cbias[r0];
        float d1 = g_d[n * 512 + r1], bb1 = cbias[r1];
        __half* row0 = y0n + (size_t)r0 * 4356;
        __half* row1 = y0n + (size_t)r1 * 4356;
        #pragma unroll
        for (int nt = 0; nt < 8; nt++) {
            int p = p0 + wn * 64 + nt * 8 + 2 * (lane & 3);
            if (p + 1 < 4356) {
                *(__half2*)(row0 + p) = __floats2half2_rn(C[mt][nt][0] * d0 + bb0, C[mt][nt][1] * d0 + bb0);
                *(__half2*)(row1 + p) = __floats2half2_rn(C[mt][nt][2] * d1 + bb1, C[mt][nt][3] * d1 + bb1);
            } else if (p < 4356) {
                row0[p] = __float2half(C[mt][nt][0] * d0 + bb0);
                row1[p] = __float2half(C[mt][nt][2] * d1 + bb1);
            }
        }
    }
}

// ---------------- K7: fused filtered_lrelu (register-blocked) ----------------
// Region A: SIN[76][68] (5168) then Z[138][141] (19458, +8 pad)
// Region B: T1[138][77] (+8 pad) then V[64][145]
#define TS 77
#define ZS 141
#define VS 145
#define RA_SZ 19466
#define RB_SZ 10634
__global__ __launch_bounds__(512) void k_flrelu(const float* __restrict__ uf,
                                                const float* __restrict__ dfl,
                                                float* __restrict__ out) {
    extern __shared__ float sm[];
    float* A = sm;
    float* B = sm + RA_SZ;
    __shared__ float fs[12], ds[12];

    int tid = threadIdx.x;
    if (tid < 12) fs[tid] = uf[tid];
    else if (tid < 24) ds[tid - 12] = dfl[tid - 12];

    const __half* img = g_y0h + (size_t)blockIdx.x * (66 * 66);

    // P0: SIN in A, zero-fill T1 region
    for (int idx = tid; idx < 76 * 68; idx += 512) {
        int row = idx / 68, col = idx - row * 68;
        int ry = row - 5;
        float v = 0.f;
        if (ry >= 0 && ry < 66 && col < 66) v = __half2float(img[ry * 66 + col]);
        A[idx] = v;
    }
    for (int idx = tid; idx < RB_SZ; idx += 512) B[idx] = 0.f;
    __syncthreads();

    // P1: vertical up-FIR -> T1[uy][x+5]; pairs uy=(2m,2m+1) share rows m+1..m+6
    for (int idx = tid; idx < 66 * 12; idx += 512) {
        int x = idx % 66, mb = idx / 66;
        int m0 = mb * 6;
        float av[11];
        #pragma unroll
        for (int j = 0; j < 11; j++) av[j] = A[(m0 + 1 + j) * 68 + x];
        #pragma unroll
        for (int j2 = 0; j2 < 6; j2++) {
            int m = m0 + j2;
            if (m < 69) {
                float se = 0.f, so = 0.f;
                #pragma unroll
                for (int k = 0; k < 6; k++) {
                    se += fs[1 + 2 * k] * av[j2 + k];
                    so += fs[2 * k]     * av[j2 + k];
                }
                B[(2 * m) * TS + x + 5]     = se;
                B[(2 * m + 1) * TS + x + 5] = so;
            }
        }
    }
    __syncthreads();

    // P2: horizontal up-FIR + gain4 + lrelu*sqrt2 + clamp -> Z[row][ux] in A
    for (int idx = tid; idx < 138 * 12; idx += 512) {
        int mb = idx % 12, row = idx / 12;
        int m0 = mb * 6;
        float tv[11];
        #pragma unroll
        for (int j = 0; j < 11; j++) tv[j] = B[row * TS + m0 + 1 + j];
        #pragma unroll
        for (int j2 = 0; j2 < 6; j2++) {
            int m = m0 + j2;
            if (m < 69) {
                float ze = 0.f, zo = 0.f;
                #pragma unroll
                for (int k = 0; k < 6; k++) {
                    ze += fs[1 + 2 * k] * tv[j2 + k];
                    zo += fs[2 * k]     * tv[j2 + k];
                }
                ze *= 4.f; zo *= 4.f;
                ze = (ze >= 0.f ? ze : 0.2f * ze) * 1.4142135623730951f;
                zo = (zo >= 0.f ? zo : 0.2f * zo) * 1.4142135623730951f;
                ze = fminf(fmaxf(ze, -256.f), 256.f);
                zo = fminf(fmaxf(zo, -256.f), 256.f);
                A[row * ZS + 2 * m]     = ze;
                A[row * ZS + 2 * m + 1] = zo;
            }
        }
    }
    __syncthreads();

    // P3: horizontal down-FIR -> V[ox][row] (transposed) in B
    for (int idx = tid; idx < 138 * 8; idx += 512) {
        int row = idx % 138, strip = idx / 138;
        int ox0 = strip * 8;
        float zv[26];
        #pragma unroll
        for (int j = 0; j < 26; j++) zv[j] = A[row * ZS + 2 * ox0 + j];
        #pragma unroll
        for (int p = 0; p < 8; p++) {
            float acc = 0.f;
            #pragma unroll
            for (int t = 0; t < 12; t++) acc += ds[t] * zv[2 * p + t];
            B[(ox0 + p) * VS + row] = acc;
        }
    }
    __syncthreads();

    // P4: vertical down-FIR -> out
    float* o = out + (size_t)blockIdx.x * (64 * 64);
    {
        int ox = tid % 64, strip = tid / 64;       // 512 threads = 64 x 8 exactly
        int oy0 = strip * 8;
        float vv[26];
        #pragma unroll
        for (int j = 0; j < 26; j++) vv[j] = B[ox * VS + 2 * oy0 + j];
        #pragma unroll
        for (int p = 0; p < 8; p++) {
            float acc = 0.f;
            #pragma unroll
            for (int t = 0; t < 12; t++) acc += ds[t] * vv[2 * p + t];
            o[(oy0 + p) * 64 + ox] = acc;
        }
    }
}

// ---------------- launch ----------------
extern "C" void kernel_launch(void* const* d_in, const int* in_sizes, int n_in,
                              void* d_out, int out_size) {
    const float* x  = (const float*)d_in[0];
    const float* w  = (const float*)d_in[1];
    const float* aw = (const float*)d_in[2];
    const float* ab = (const float*)d_in[3];
    const float* cw = (const float*)d_in[4];
    const float* cb = (const float*)d_in[5];
    const float* uf = (const float*)d_in[6];
    const float* df = (const float*)d_in[7];
    float* out = (float*)d_out;
    (void)in_sizes; (void)n_in; (void)out_size;

    cudaFuncSetAttribute(k_conv,   cudaFuncAttributeMaxDynamicSharedMemorySize, 3 * STAGE_B);
    cudaFuncSetAttribute(k_flrelu, cudaFuncAttributeMaxDynamicSharedMemorySize, (RA_SZ + RB_SZ) * 4);

    k_styles<<<NB, 512>>>(w, aw, ab);
    k_snorm<<<1, 256>>>();
    k_rn<<<COUT, 256>>>(cw);
    k_d<<<COUT, 128>>>();
    k_pad<<<dim3(68, NB), 512>>>(x);
    k_conv<<<dim3(18, 4, NB), 256, 3 * STAGE_B>>>(cb);
    k_flrelu<<<NB * COUT, 512, (RA_SZ + RB_SZ) * 4>>>(uf, df, out);
}

// round 6
// speedup vs baseline: 1.2283x; 1.2283x over previous
#include <cuda_runtime.h>
#include <cuda_fp16.h>
#include <cstdint>

#define NB   16
#define CIN  512
#define COUT 512
#define RES  64

// ---------------- device scratch ----------------
__device__ float  g_styles[NB * CIN];
__device__ float  g_s[NB * CIN];
__device__ float  g_rn[COUT];
__device__ float  g_qraw[COUT * CIN];
__device__ float  g_d[NB * COUT];
__device__ __half g_wth[9 * COUT * CIN];            // [kk][oc][i] fp16
__device__ __half g_xph[NB * 68 * 68 * CIN];        // NHWC padded, style-scaled fp16
__device__ __half g_y0h[NB * COUT * 66 * 66];       // conv out (+d, +bias) fp16

// ---------------- helpers ----------------
__device__ __forceinline__ uint32_t smem_u32(const void* p) {
    uint32_t a;
    asm("{ .reg .u64 t; cvta.to.shared.u64 t, %1; cvt.u32.u64 %0, t; }" : "=r"(a) : "l"(p));
    return a;
}
__device__ __forceinline__ uint32_t swz(uint32_t o) { return o ^ ((o >> 3) & 0x70); }

__device__ __forceinline__ void ldsm4(uint32_t* r, uint32_t addr) {
    asm volatile("ldmatrix.sync.aligned.m8n8.x4.shared.b16 {%0,%1,%2,%3}, [%4];"
        : "=r"(r[0]), "=r"(r[1]), "=r"(r[2]), "=r"(r[3]) : "r"(addr));
}
__device__ __forceinline__ void mma16816(float* c, const uint32_t* a, uint32_t b0, uint32_t b1) {
    asm volatile("mma.sync.aligned.m16n8k16.row.col.f32.f16.f16.f32 "
        "{%0,%1,%2,%3}, {%4,%5,%6,%7}, {%8,%9}, {%0,%1,%2,%3};"
        : "+f"(c[0]), "+f"(c[1]), "+f"(c[2]), "+f"(c[3])
        : "r"(a[0]), "r"(a[1]), "r"(a[2]), "r"(a[3]), "r"(b0), "r"(b1));
}

// ---------------- K1: styles ----------------
__global__ void k_styles(const float* __restrict__ w,
                         const float* __restrict__ aw,
                         const float* __restrict__ ab) {
    int n = blockIdx.x, tid = threadIdx.x;
    __shared__ float wsh[512];
    wsh[tid] = w[n * 512 + tid];
    __syncthreads();
    int warp = tid >> 5, lane = tid & 31;
    for (int i = warp; i < 512; i += 16) {
        float acc = 0.f;
        const float* row = aw + (size_t)i * 512;
        for (int j = lane; j < 512; j += 32) acc += wsh[j] * row[j];
        #pragma unroll
        for (int off = 16; off; off >>= 1) acc += __shfl_down_sync(0xffffffffu, acc, off);
        if (lane == 0) g_styles[n * 512 + i] = acc * 0.04419417382415922f + ab[i];
    }
}

// ---------------- K2: s normalize ----------------
__global__ void k_snorm() {
    int tid = threadIdx.x;
    __shared__ float red[256];
    __shared__ float rstd_s;
    float a = 0.f;
    for (int idx = tid; idx < NB * CIN; idx += 256) { float v = g_styles[idx]; a += v * v; }
    red[tid] = a; __syncthreads();
    for (int off = 128; off; off >>= 1) { if (tid < off) red[tid] += red[tid + off]; __syncthreads(); }
    if (tid == 0) rstd_s = rsqrtf(red[0] / (float)(NB * CIN));
    __syncthreads();
    float rs = rstd_s;
    for (int idx = tid; idx < NB * CIN; idx += 256) g_s[idx] = g_styles[idx] * rs;
}

// ---------------- K3: rn, qraw, wth[kk][oc][i] fp16 ----------------
__global__ void k_rn(const float* __restrict__ cw) {
    int o = blockIdx.x, tid = threadIdx.x;
    const float* cwo = cw + (size_t)o * 4608;
    __shared__ float red[256];
    __shared__ float rn_s;
    float a = 0.f;
    for (int idx = tid; idx < 4608; idx += 256) { float v = cwo[idx]; a += v * v; }
    red[tid] = a; __syncthreads();
    for (int off = 128; off; off >>= 1) { if (tid < off) red[tid] += red[tid + off]; __syncthreads(); }
    if (tid == 0) { rn_s = rsqrtf(red[0] / 4608.f); g_rn[o] = rn_s; }
    __syncthreads();
    float rn = rn_s;
    for (int i = tid; i < 512; i += 256) {
        float q = 0.f;
        #pragma unroll
        for (int kk = 0; kk < 9; kk++) { float v = cwo[i * 9 + kk]; q += v * v; }
        g_qraw[o * 512 + i] = q;
    }
    #pragma unroll
    for (int kk = 0; kk < 9; kk++)
        for (int i = tid; i < 512; i += 256)
            g_wth[((size_t)(kk * 512) + o) * 512 + i] = __float2half(cwo[i * 9 + kk] * rn);
}

// ---------------- K4: d[n][o]  (grid 512, block 128) ----------------
__global__ void k_d() {
    int o = blockIdx.x, tid = threadIdx.x;
    int warp = tid >> 5, lane = tid & 31;
    __shared__ float qsh[512];
    for (int i = tid; i < 512; i += 128) qsh[i] = g_qraw[o * 512 + i];
    __syncthreads();
    float rn = g_rn[o];
    for (int n = warp; n < NB; n += 4) {
        float acc = 0.f;
        for (int i = lane; i < 512; i += 32) {
            float sv = g_s[n * 512 + i];
            acc += sv * sv * qsh[i];
        }
        #pragma unroll
        for (int off = 16; off; off >>= 1) acc += __shfl_down_sync(0xffffffffu, acc, off);
        if (lane == 0) g_d[n * 512 + o] = rsqrtf(rn * rn * acc + 1e-8f);
    }
}

// ---------------- K5: NHWC padded, scaled input fp16 ----------------
__global__ __launch_bounds__(512) void k_pad(const float* __restrict__ x) {
    int yy = blockIdx.x, n = blockIdx.y, tid = threadIdx.x;
    __shared__ float ts[128][65];
    __half* orow = g_xph + ((size_t)(n * 68 + yy) * 68) * 512;
    bool inner = (yy >= 2 && yy < 66);
    for (int ct = 0; ct < 4; ct++) {
        __syncthreads();
        if (inner) {
            #pragma unroll
            for (int it = 0; it < 16; it++) {
                int idx = it * 512 + tid;
                int c = idx >> 6, xx = idx & 63;
                int cg = ct * 128 + c;
                ts[c][xx] = x[(((size_t)(n * 512) + cg) * 64 + (yy - 2)) * 64 + xx] * g_s[n * 512 + cg];
            }
        }
        __syncthreads();
        #pragma unroll
        for (int it = 0; it < 17; it++) {
            int idx = it * 512 + tid;
            if (idx < 68 * 128) {
                int xx = idx >> 7, c = idx & 127;
                float v = 0.f;
                if (inner && xx >= 2 && xx < 66) v = ts[c][xx - 2];
                orow[xx * 512 + ct * 128 + c] = __float2half(v);
            }
        }
    }
}

// ---------------- K6: conv via mma.sync fp16 implicit GEMM ----------------
#define STAGE_B 49152
__global__ __launch_bounds__(256, 1) void k_conv(const float* __restrict__ cbias) {
    extern __shared__ char smem[];
    uint32_t sb = smem_u32(smem);
    int tid = threadIdx.x, lane = tid & 31, wid = tid >> 5;
    int pt = blockIdx.x, ot = blockIdx.y, n = blockIdx.z;
    int p0 = pt * 256;
    int wm = wid & 1, wn = wid >> 1;

    float C[4][8][4];
    #pragma unroll
    for (int i = 0; i < 4; i++)
        #pragma unroll
        for (int j = 0; j < 8; j++)
            #pragma unroll
            for (int k = 0; k < 4; k++) C[i][j][k] = 0.f;

    int ch = tid & 7;
    int trow = tid >> 3;

    uint32_t browoff[8];
    #pragma unroll
    for (int b = 0; b < 8; b++) {
        int row = b * 32 + trow;
        int p = p0 + row; if (p > 4355) p = 4355;
        int y = p / 66, xx = p - y * 66;
        browoff[b] = ((uint32_t)(n * 68 + y) * 68 + xx) * 512;
    }
    uint32_t sA_st[4], sB_st[8];
    #pragma unroll
    for (int a = 0; a < 4; a++) sA_st[a] = swz(((a * 32 + trow) * 128) + ch * 16);
    #pragma unroll
    for (int b = 0; b < 8; b++) sB_st[b] = 16384 + swz(((b * 32 + trow) * 128) + ch * 16);

#define LOAD_TILE(js_, slot_) do { \
    int kk_ = (js_) >> 3; int i0_ = ((js_) & 7) << 6; \
    int ky_ = kk_ / 3, kx_ = kk_ - ky_ * 3; \
    uint32_t stb_ = sb + (uint32_t)(slot_) * STAGE_B; \
    const __half* ap_ = g_wth + ((size_t)(kk_ * 512 + ot * 128)) * 512 + i0_ + ch * 8; \
    _Pragma("unroll") \
    for (int a_ = 0; a_ < 4; a_++) { \
        uint32_t sa_ = stb_ + sA_st[a_]; \
        const __half* ga_ = ap_ + (size_t)(a_ * 32 + trow) * 512; \
        asm volatile("cp.async.cg.shared.global [%0], [%1], 16;" :: "r"(sa_), "l"(ga_)); \
    } \
    uint32_t koff_ = (uint32_t)(ky_ * 68 + kx_) * 512 + i0_ + ch * 8; \
    _Pragma("unroll") \
    for (int b_ = 0; b_ < 8; b_++) { \
        uint32_t sa_ = stb_ + sB_st[b_]; \
        const __half* gb_ = g_xph + browoff[b_] + koff_; \
        asm volatile("cp.async.cg.shared.global [%0], [%1], 16;" :: "r"(sa_), "l"(gb_)); \
    } \
    asm volatile("cp.async.commit_group;" ::: "memory"); \
} while (0)

    LOAD_TILE(0, 0);
    LOAD_TILE(1, 1);

    uint32_t aRow = wm * 64 + (lane & 15);
    uint32_t aCol = (uint32_t)(lane >> 4);
    uint32_t bRow = wn * 64 + ((lane >> 4) << 3) + (lane & 7);
    uint32_t bCol = (uint32_t)((lane >> 3) & 1);

    for (int js = 0; js < 72; js++) {
        int cur = js % 3;
        asm volatile("cp.async.wait_group 1;" ::: "memory");
        __syncthreads();
        if (js + 2 < 72) { LOAD_TILE(js + 2, (js + 2) % 3); }
        else { asm volatile("cp.async.commit_group;" ::: "memory"); }

        uint32_t sA = sb + (uint32_t)cur * STAGE_B;
        uint32_t sB = sA + 16384;
        #pragma unroll
        for (int ks = 0; ks < 4; ks++) {
            uint32_t af[4][4], bf[4][4];
            #pragma unroll
            for (int mt = 0; mt < 4; mt++)
                ldsm4(af[mt], sA + swz((aRow + mt * 16) * 128 + (ks * 2 + aCol) * 16));
            #pragma unroll
            for (int bt = 0; bt < 4; bt++)
                ldsm4(bf[bt], sB + swz((bRow + bt * 16) * 128 + (ks * 2 + bCol) * 16));
            #pragma unroll
            for (int mt = 0; mt < 4; mt++)
                #pragma unroll
                for (int bt = 0; bt < 4; bt++) {
                    mma16816(C[mt][2 * bt],     af[mt], bf[bt][0], bf[bt][1]);
                    mma16816(C[mt][2 * bt + 1], af[mt], bf[bt][2], bf[bt][3]);
                }
        }
    }

    // ---- epilogue: *d + bias -> g_y0h (fp16) ----
    int obase = ot * 128 + wm * 64;
    __half* y0n = g_y0h + (size_t)n * 512 * 4356;
    #pragma unroll
    for (int mt = 0; mt < 4; mt++) {
        int r0 = obase + mt * 16 + (lane >> 2);
        int r1 = r0 + 8;
        float d0 = g_d[n * 512 + r0], bb0 = cbias[r0];
        float d1 = g_d[n * 512 + r1], bb1 = cbias[r1];
        __half* row0 = y0n + (size_t)r0 * 4356;
        __half* row1 = y0n + (size_t)r1 * 4356;
        #pragma unroll
        for (int nt = 0; nt < 8; nt++) {
            int p = p0 + wn * 64 + nt * 8 + 2 * (lane & 3);
            if (p + 1 < 4356) {
                *(__half2*)(row0 + p) = __floats2half2_rn(C[mt][nt][0] * d0 + bb0, C[mt][nt][1] * d0 + bb0);
                *(__half2*)(row1 + p) = __floats2half2_rn(C[mt][nt][2] * d1 + bb1, C[mt][nt][3] * d1 + bb1);
            } else if (p < 4356) {
                row0[p] = __float2half(C[mt][nt][0] * d0 + bb0);
                row1[p] = __float2half(C[mt][nt][2] * d1 + bb1);
            }
        }
    }
}

// ---------------- K7: fused filtered_lrelu (R3 structure, fp16 input) ----------------
__global__ __launch_bounds__(512) void k_flrelu(const float* __restrict__ uf,
                                                const float* __restrict__ dfl,
                                                float* __restrict__ out) {
    extern __shared__ float sm[];
    float* A = sm;                 // SIN [76][68] then Z [138][140]
    float* B = sm + 19320;         // T1 [138][76] then V [138][64]
    __shared__ float fs[12], ds[12];

    int tid = threadIdx.x;
    if (tid < 12) fs[tid] = uf[tid];
    else if (tid < 24) ds[tid - 12] = dfl[tid - 12];

    const __half* img = g_y0h + (size_t)blockIdx.x * (66 * 66);

    for (int idx = tid; idx < 76 * 68; idx += 512) {
        int row = idx / 68, col = idx % 68;
        int ry = row - 5;
        float v = 0.f;
        if (ry >= 0 && ry < 66 && col < 66) v = __half2float(img[ry * 66 + col]);
        A[idx] = v;
    }
    __syncthreads();

    for (int idx = tid; idx < 138 * 76; idx += 512) {
        int uy = idx / 76, cc2 = idx - uy * 76;
        float acc = 0.f;
        if (cc2 >= 5 && cc2 < 71) {
            int x = cc2 - 5;
            int t0 = (9 - uy) & 1;
            int q0 = (uy + t0 - 9) >> 1;
            #pragma unroll
            for (int k = 0; k < 6; k++)
                acc += fs[t0 + 2 * k] * A[(q0 + k + 5) * 68 + x];
        }
        B[idx] = acc;
    }
    __syncthreads();

    for (int idx = tid; idx < 138 * 138; idx += 512) {
        int uy = idx / 138, ux = idx - uy * 138;
        int t0 = (9 - ux) & 1;
        int q0 = (ux + t0 - 9) >> 1;
        float acc = 0.f;
        #pragma unroll
        for (int k = 0; k < 6; k++)
            acc += fs[t0 + 2 * k] * B[uy * 76 + (q0 + k + 5)];
        float y4 = 4.f * acc;
        float l = (y4 >= 0.f ? y4 : 0.2f * y4) * 1.4142135623730951f;
        l = fminf(fmaxf(l, -256.f), 256.f);
        A[uy * 140 + ux] = l;
    }
    __syncthreads();

    for (int idx = tid; idx < 138 * 64; idx += 512) {
        int uy = idx / 64, ox = idx - uy * 64;
        float acc = 0.f;
        #pragma unroll
        for (int tt = 0; tt < 12; tt++)
            acc += ds[tt] * A[uy * 140 + 2 * ox + tt];
        B[uy * 64 + ox] = acc;
    }
    __syncthreads();

    float* o = out + (size_t)blockIdx.x * (64 * 64);
    for (int idx = tid; idx < 64 * 64; idx += 512) {
        int oy = idx >> 6, ox = idx & 63;
        float acc = 0.f;
        #pragma unroll
        for (int i = 0; i < 12; i++)
            acc += ds[i] * B[(2 * oy + i) * 64 + ox];
        o[idx] = acc;
    }
}

// ---------------- launch ----------------
extern "C" void kernel_launch(void* const* d_in, const int* in_sizes, int n_in,
                              void* d_out, int out_size) {
    const float* x  = (const float*)d_in[0];
    const float* w  = (const float*)d_in[1];
    const float* aw = (const float*)d_in[2];
    const float* ab = (const float*)d_in[3];
    const float* cw = (const float*)d_in[4];
    const float* cb = (const float*)d_in[5];
    const float* uf = (const float*)d_in[6];
    const float* df = (const float*)d_in[7];
    float* out = (float*)d_out;
    (void)in_sizes; (void)n_in; (void)out_size;

    cudaFuncSetAttribute(k_conv,   cudaFuncAttributeMaxDynamicSharedMemorySize, 3 * STAGE_B);
    cudaFuncSetAttribute(k_flrelu, cudaFuncAttributeMaxDynamicSharedMemorySize, 119232);

    k_styles<<<NB, 512>>>(w, aw, ab);
    k_snorm<<<1, 256>>>();
    k_rn<<<COUT, 256>>>(cw);
    k_d<<<COUT, 128>>>();
    k_pad<<<dim3(68, NB), 512>>>(x);
    k_conv<<<dim3(18, 4, NB), 256, 3 * STAGE_B>>>(cb);
    k_flrelu<<<NB * COUT, 512, 119232>>>(uf, df, out);
}

// round 7
// speedup vs baseline: 1.3266x; 1.0800x over previous
#include <cuda_runtime.h>
#include <cuda_fp16.h>
#include <cstdint>

#define NB   16
#define CIN  512
#define COUT 512
#define RES  64

// ---------------- device scratch ----------------
__device__ float  g_styles[NB * CIN];
__device__ float  g_s[NB * CIN];
__device__ float  g_rn[COUT];
__device__ float  g_qraw[COUT * CIN];
__device__ float  g_d[NB * COUT];
__device__ __half g_wth[9 * COUT * CIN];            // [kk][oc][i] fp16
__device__ __half g_xph[NB * 68 * 68 * CIN];        // NHWC padded, style-scaled fp16
__device__ __half g_y0h[NB * COUT * 66 * 66];       // conv out (+d, +bias) fp16

// ---------------- helpers ----------------
__device__ __forceinline__ uint32_t smem_u32(const void* p) {
    uint32_t a;
    asm("{ .reg .u64 t; cvta.to.shared.u64 t, %1; cvt.u32.u64 %0, t; }" : "=r"(a) : "l"(p));
    return a;
}
__device__ __forceinline__ uint32_t swz(uint32_t o) { return o ^ ((o >> 3) & 0x70); }

__device__ __forceinline__ void ldsm4(uint32_t* r, uint32_t addr) {
    asm volatile("ldmatrix.sync.aligned.m8n8.x4.shared.b16 {%0,%1,%2,%3}, [%4];"
        : "=r"(r[0]), "=r"(r[1]), "=r"(r[2]), "=r"(r[3]) : "r"(addr));
}
__device__ __forceinline__ void mma16816(float* c, const uint32_t* a, uint32_t b0, uint32_t b1) {
    asm volatile("mma.sync.aligned.m16n8k16.row.col.f32.f16.f16.f32 "
        "{%0,%1,%2,%3}, {%4,%5,%6,%7}, {%8,%9}, {%0,%1,%2,%3};"
        : "+f"(c[0]), "+f"(c[1]), "+f"(c[2]), "+f"(c[3])
        : "r"(a[0]), "r"(a[1]), "r"(a[2]), "r"(a[3]), "r"(b0), "r"(b1));
}

// ---------------- K1: styles ----------------
__global__ void k_styles(const float* __restrict__ w,
                         const float* __restrict__ aw,
                         const float* __restrict__ ab) {
    int n = blockIdx.x, tid = threadIdx.x;
    __shared__ float wsh[512];
    wsh[tid] = w[n * 512 + tid];
    __syncthreads();
    int warp = tid >> 5, lane = tid & 31;
    for (int i = warp; i < 512; i += 16) {
        float acc = 0.f;
        const float* row = aw + (size_t)i * 512;
        for (int j = lane; j < 512; j += 32) acc += wsh[j] * row[j];
        #pragma unroll
        for (int off = 16; off; off >>= 1) acc += __shfl_down_sync(0xffffffffu, acc, off);
        if (lane == 0) g_styles[n * 512 + i] = acc * 0.04419417382415922f + ab[i];
    }
}

// ---------------- K2: s normalize ----------------
__global__ void k_snorm() {
    int tid = threadIdx.x;
    __shared__ float red[256];
    __shared__ float rstd_s;
    float a = 0.f;
    for (int idx = tid; idx < NB * CIN; idx += 256) { float v = g_styles[idx]; a += v * v; }
    red[tid] = a; __syncthreads();
    for (int off = 128; off; off >>= 1) { if (tid < off) red[tid] += red[tid + off]; __syncthreads(); }
    if (tid == 0) rstd_s = rsqrtf(red[0] / (float)(NB * CIN));
    __syncthreads();
    float rs = rstd_s;
    for (int idx = tid; idx < NB * CIN; idx += 256) g_s[idx] = g_styles[idx] * rs;
}

// ---------------- K3: rn, qraw, wth[kk][oc][i] fp16 ----------------
__global__ void k_rn(const float* __restrict__ cw) {
    int o = blockIdx.x, tid = threadIdx.x;
    const float* cwo = cw + (size_t)o * 4608;
    __shared__ float red[256];
    __shared__ float rn_s;
    float a = 0.f;
    for (int idx = tid; idx < 4608; idx += 256) { float v = cwo[idx]; a += v * v; }
    red[tid] = a; __syncthreads();
    for (int off = 128; off; off >>= 1) { if (tid < off) red[tid] += red[tid + off]; __syncthreads(); }
    if (tid == 0) { rn_s = rsqrtf(red[0] / 4608.f); g_rn[o] = rn_s; }
    __syncthreads();
    float rn = rn_s;
    for (int i = tid; i < 512; i += 256) {
        float q = 0.f;
        #pragma unroll
        for (int kk = 0; kk < 9; kk++) { float v = cwo[i * 9 + kk]; q += v * v; }
        g_qraw[o * 512 + i] = q;
    }
    #pragma unroll
    for (int kk = 0; kk < 9; kk++)
        for (int i = tid; i < 512; i += 256)
            g_wth[((size_t)(kk * 512) + o) * 512 + i] = __float2half(cwo[i * 9 + kk] * rn);
}

// ---------------- K4: d[n][o]  (grid 512, block 128) ----------------
__global__ void k_d() {
    int o = blockIdx.x, tid = threadIdx.x;
    int warp = tid >> 5, lane = tid & 31;
    __shared__ float qsh[512];
    for (int i = tid; i < 512; i += 128) qsh[i] = g_qraw[o * 512 + i];
    __syncthreads();
    float rn = g_rn[o];
    for (int n = warp; n < NB; n += 4) {
        float acc = 0.f;
        for (int i = lane; i < 512; i += 32) {
            float sv = g_s[n * 512 + i];
            acc += sv * sv * qsh[i];
        }
        #pragma unroll
        for (int off = 16; off; off >>= 1) acc += __shfl_down_sync(0xffffffffu, acc, off);
        if (lane == 0) g_d[n * 512 + o] = rsqrtf(rn * rn * acc + 1e-8f);
    }
}

// ---------------- K5: NHWC padded, scaled input fp16 ----------------
__global__ __launch_bounds__(512) void k_pad(const float* __restrict__ x) {
    int yy = blockIdx.x, n = blockIdx.y, tid = threadIdx.x;
    __shared__ float ts[128][65];
    __half* orow = g_xph + ((size_t)(n * 68 + yy) * 68) * 512;
    bool inner = (yy >= 2 && yy < 66);
    for (int ct = 0; ct < 4; ct++) {
        __syncthreads();
        if (inner) {
            #pragma unroll
            for (int it = 0; it < 16; it++) {
                int idx = it * 512 + tid;
                int c = idx >> 6, xx = idx & 63;
                int cg = ct * 128 + c;
                ts[c][xx] = x[(((size_t)(n * 512) + cg) * 64 + (yy - 2)) * 64 + xx] * g_s[n * 512 + cg];
            }
        }
        __syncthreads();
        #pragma unroll
        for (int it = 0; it < 17; it++) {
            int idx = it * 512 + tid;
            if (idx < 68 * 128) {
                int xx = idx >> 7, c = idx & 127;
                float v = 0.f;
                if (inner && xx >= 2 && xx < 66) v = ts[c][xx - 2];
                orow[xx * 512 + ct * 128 + c] = __float2half(v);
            }
        }
    }
}

// ---------------- K6: conv via mma.sync fp16 implicit GEMM ----------------
// CTA tile 128 oc x 128 px, warp tile 32x64 (4x2 warps). 3-stage, 2 CTA/SM.
#define STAGE_B 32768
__global__ __launch_bounds__(256, 2) void k_conv(const float* __restrict__ cbias) {
    extern __shared__ char smem[];
    uint32_t sb = smem_u32(smem);
    int tid = threadIdx.x, lane = tid & 31, wid = tid >> 5;
    int pt = blockIdx.x, ot = blockIdx.y, n = blockIdx.z;
    int p0 = pt * 128;
    int wm = wid & 3, wn = wid >> 2;

    float C[2][8][4];
    #pragma unroll
    for (int i = 0; i < 2; i++)
        #pragma unroll
        for (int j = 0; j < 8; j++)
            #pragma unroll
            for (int k = 0; k < 4; k++) C[i][j][k] = 0.f;

    int ch = tid & 7;
    int trow = tid >> 3;

    uint32_t browoff[4];
    #pragma unroll
    for (int b = 0; b < 4; b++) {
        int row = b * 32 + trow;
        int p = p0 + row; if (p > 4355) p = 4355;
        int y = p / 66, xx = p - y * 66;
        browoff[b] = ((uint32_t)(n * 68 + y) * 68 + xx) * 512;
    }
    uint32_t sA_st[4], sB_st[4];
    #pragma unroll
    for (int a = 0; a < 4; a++) sA_st[a] = swz(((a * 32 + trow) * 128) + ch * 16);
    #pragma unroll
    for (int b = 0; b < 4; b++) sB_st[b] = 16384 + swz(((b * 32 + trow) * 128) + ch * 16);

#define LOAD_TILE(js_, slot_) do { \
    int kk_ = (js_) >> 3; int i0_ = ((js_) & 7) << 6; \
    int ky_ = kk_ / 3, kx_ = kk_ - ky_ * 3; \
    uint32_t stb_ = sb + (uint32_t)(slot_) * STAGE_B; \
    const __half* ap_ = g_wth + ((size_t)(kk_ * 512 + ot * 128)) * 512 + i0_ + ch * 8; \
    _Pragma("unroll") \
    for (int a_ = 0; a_ < 4; a_++) { \
        uint32_t sa_ = stb_ + sA_st[a_]; \
        const __half* ga_ = ap_ + (size_t)(a_ * 32 + trow) * 512; \
        asm volatile("cp.async.cg.shared.global [%0], [%1], 16;" :: "r"(sa_), "l"(ga_)); \
    } \
    uint32_t koff_ = (uint32_t)(ky_ * 68 + kx_) * 512 + i0_ + ch * 8; \
    _Pragma("unroll") \
    for (int b_ = 0; b_ < 4; b_++) { \
        uint32_t sa_ = stb_ + sB_st[b_]; \
        const __half* gb_ = g_xph + browoff[b_] + koff_; \
        asm volatile("cp.async.cg.shared.global [%0], [%1], 16;" :: "r"(sa_), "l"(gb_)); \
    } \
    asm volatile("cp.async.commit_group;" ::: "memory"); \
} while (0)

    LOAD_TILE(0, 0);
    LOAD_TILE(1, 1);

    uint32_t aRow = wm * 32 + (lane & 15);
    uint32_t aCol = (uint32_t)(lane >> 4);
    uint32_t bRow = wn * 64 + ((lane >> 4) << 3) + (lane & 7);
    uint32_t bCol = (uint32_t)((lane >> 3) & 1);

    for (int js = 0; js < 72; js++) {
        int cur = js % 3;
        asm volatile("cp.async.wait_group 1;" ::: "memory");
        __syncthreads();
        if (js + 2 < 72) { LOAD_TILE(js + 2, (js + 2) % 3); }
        else { asm volatile("cp.async.commit_group;" ::: "memory"); }

        uint32_t sA = sb + (uint32_t)cur * STAGE_B;
        uint32_t sB = sA + 16384;
        #pragma unroll
        for (int ks = 0; ks < 4; ks++) {
            uint32_t af[2][4], bf[4][4];
            #pragma unroll
            for (int mt = 0; mt < 2; mt++)
                ldsm4(af[mt], sA + swz((aRow + mt * 16) * 128 + (ks * 2 + aCol) * 16));
            #pragma unroll
            for (int bt = 0; bt < 4; bt++)
                ldsm4(bf[bt], sB + swz((bRow + bt * 16) * 128 + (ks * 2 + bCol) * 16));
            #pragma unroll
            for (int mt = 0; mt < 2; mt++)
                #pragma unroll
                for (int bt = 0; bt < 4; bt++) {
                    mma16816(C[mt][2 * bt],     af[mt], bf[bt][0], bf[bt][1]);
                    mma16816(C[mt][2 * bt + 1], af[mt], bf[bt][2], bf[bt][3]);
                }
        }
    }

    // ---- epilogue: *d + bias -> g_y0h (fp16) ----
    int obase = ot * 128 + wm * 32;
    __half* y0n = g_y0h + (size_t)n * 512 * 4356;
    bool tail = (pt == 34);
    #pragma unroll
    for (int mt = 0; mt < 2; mt++) {
        int r0 = obase + mt * 16 + (lane >> 2);
        int r1 = r0 + 8;
        float d0 = g_d[n * 512 + r0], bb0 = cbias[r0];
        float d1 = g_d[n * 512 + r1], bb1 = cbias[r1];
        __half* row0 = y0n + (size_t)r0 * 4356;
        __half* row1 = y0n + (size_t)r1 * 4356;
        #pragma unroll
        for (int nt = 0; nt < 8; nt++) {
            int p = p0 + wn * 64 + nt * 8 + 2 * (lane & 3);
            if (!tail || p + 1 < 4356) {
                *(__half2*)(row0 + p) = __floats2half2_rn(C[mt][nt][0] * d0 + bb0, C[mt][nt][1] * d0 + bb0);
                *(__half2*)(row1 + p) = __floats2half2_rn(C[mt][nt][2] * d1 + bb1, C[mt][nt][3] * d1 + bb1);
            } else if (p < 4356) {
                row0[p] = __float2half(C[mt][nt][0] * d0 + bb0);
                row1[p] = __float2half(C[mt][nt][2] * d1 + bb1);
            }
        }
    }
}

// ---------------- K7: fused filtered_lrelu (R3 structure, fp16 input) ----------------
__global__ __launch_bounds__(512) void k_flrelu(const float* __restrict__ uf,
                                                const float* __restrict__ dfl,
                                                float* __restrict__ out) {
    extern __shared__ float sm[];
    float* A = sm;                 // SIN [76][68] then Z [138][140]
    float* B = sm + 19320;         // T1 [138][76] then V [138][64]
    __shared__ float fs[12], ds[12];

    int tid = threadIdx.x;
    if (tid < 12) fs[tid] = uf[tid];
    else if (tid < 24) ds[tid - 12] = dfl[tid - 12];

    const __half* img = g_y0h + (size_t)blockIdx.x * (66 * 66);

    for (int idx = tid; idx < 76 * 68; idx += 512) {
        int row = idx / 68, col = idx % 68;
        int ry = row - 5;
        float v = 0.f;
        if (ry >= 0 && ry < 66 && col < 66) v = __half2float(img[ry * 66 + col]);
        A[idx] = v;
    }
    __syncthreads();

    for (int idx = tid; idx < 138 * 76; idx += 512) {
        int uy = idx / 76, cc2 = idx - uy * 76;
        float acc = 0.f;
        if (cc2 >= 5 && cc2 < 71) {
            int x = cc2 - 5;
            int t0 = (9 - uy) & 1;
            int q0 = (uy + t0 - 9) >> 1;
            #pragma unroll
            for (int k = 0; k < 6; k++)
                acc += fs[t0 + 2 * k] * A[(q0 + k + 5) * 68 + x];
        }
        B[idx] = acc;
    }
    __syncthreads();

    for (int idx = tid; idx < 138 * 138; idx += 512) {
        int uy = idx / 138, ux = idx - uy * 138;
        int t0 = (9 - ux) & 1;
        int q0 = (ux + t0 - 9) >> 1;
        float acc = 0.f;
        #pragma unroll
        for (int k = 0; k < 6; k++)
            acc += fs[t0 + 2 * k] * B[uy * 76 + (q0 + k + 5)];
        float y4 = 4.f * acc;
        float l = (y4 >= 0.f ? y4 : 0.2f * y4) * 1.4142135623730951f;
        l = fminf(fmaxf(l, -256.f), 256.f);
        A[uy * 140 + ux] = l;
    }
    __syncthreads();

    for (int idx = tid; idx < 138 * 64; idx += 512) {
        int uy = idx / 64, ox = idx - uy * 64;
        float acc = 0.f;
        #pragma unroll
        for (int tt = 0; tt < 12; tt++)
            acc += ds[tt] * A[uy * 140 + 2 * ox + tt];
        B[uy * 64 + ox] = acc;
    }
    __syncthreads();

    float* o = out + (size_t)blockIdx.x * (64 * 64);
    for (int idx = tid; idx < 64 * 64; idx += 512) {
        int oy = idx >> 6, ox = idx & 63;
        float acc = 0.f;
        #pragma unroll
        for (int i = 0; i < 12; i++)
            acc += ds[i] * B[(2 * oy + i) * 64 + ox];
        o[idx] = acc;
    }
}

// ---------------- launch ----------------
extern "C" void kernel_launch(void* const* d_in, const int* in_sizes, int n_in,
                              void* d_out, int out_size) {
    const float* x  = (const float*)d_in[0];
    const float* w  = (const float*)d_in[1];
    const float* aw = (const float*)d_in[2];
    const float* ab = (const float*)d_in[3];
    const float* cw = (const float*)d_in[4];
    const float* cb = (const float*)d_in[5];
    const float* uf = (const float*)d_in[6];
    const float* df = (const float*)d_in[7];
    float* out = (float*)d_out;
    (void)in_sizes; (void)n_in; (void)out_size;

    cudaFuncSetAttribute(k_conv,   cudaFuncAttributeMaxDynamicSharedMemorySize, 3 * STAGE_B);
    cudaFuncSetAttribute(k_flrelu, cudaFuncAttributeMaxDynamicSharedMemorySize, 119232);

    k_styles<<<NB, 512>>>(w, aw, ab);
    k_snorm<<<1, 256>>>();
    k_rn<<<COUT, 256>>>(cw);
    k_d<<<COUT, 128>>>();
    k_pad<<<dim3(68, NB), 512>>>(x);
    k_conv<<<dim3(35, 4, NB), 256, 3 * STAGE_B>>>(cb);
    k_flrelu<<<NB * COUT, 512, 119232>>>(uf, df, out);
}

// round 11
// speedup vs baseline: 1.5224x; 1.1476x over previous
#include <cuda_runtime.h>
#include <cuda_fp16.h>
#include <cstdint>

#define NB   16
#define CIN  512
#define COUT 512
#define RES  64

// ---------------- device scratch ----------------
__device__ float  g_styles[NB * CIN];
__device__ float  g_s[NB * CIN];
__device__ float  g_rn[COUT];
__device__ float  g_qraw[COUT * CIN];
__device__ float  g_d[NB * COUT];
__device__ __half g_wth[9 * COUT * CIN];            // [kk][oc][i] fp16
__device__ __half g_xph[NB * 68 * 68 * CIN];        // NHWC padded, style-scaled fp16
__device__ __half g_y0h[NB * COUT * 66 * 66];       // conv out (+d, +bias) fp16

// ---------------- helpers ----------------
__device__ __forceinline__ uint32_t smem_u32(const void* p) {
    uint32_t a;
    asm("{ .reg .u64 t; cvta.to.shared.u64 t, %1; cvt.u32.u64 %0, t; }" : "=r"(a) : "l"(p));
    return a;
}
__device__ __forceinline__ uint32_t swz(uint32_t o) { return o ^ ((o >> 3) & 0x70); }

__device__ __forceinline__ void ldsm4(uint32_t* r, uint32_t addr) {
    asm volatile("ldmatrix.sync.aligned.m8n8.x4.shared.b16 {%0,%1,%2,%3}, [%4];"
        : "=r"(r[0]), "=r"(r[1]), "=r"(r[2]), "=r"(r[3]) : "r"(addr));
}
__device__ __forceinline__ void mma16816(float* c, const uint32_t* a, uint32_t b0, uint32_t b1) {
    asm volatile("mma.sync.aligned.m16n8k16.row.col.f32.f16.f16.f32 "
        "{%0,%1,%2,%3}, {%4,%5,%6,%7}, {%8,%9}, {%0,%1,%2,%3};"
        : "+f"(c[0]), "+f"(c[1]), "+f"(c[2]), "+f"(c[3])
        : "r"(a[0]), "r"(a[1]), "r"(a[2]), "r"(a[3]), "r"(b0), "r"(b1));
}

// ---------------- K1: styles ----------------
__global__ void k_styles(const float* __restrict__ w,
                         const float* __restrict__ aw,
                         const float* __restrict__ ab) {
    int n = blockIdx.x, tid = threadIdx.x;
    __shared__ float wsh[512];
    wsh[tid] = w[n * 512 + tid];
    __syncthreads();
    int warp = tid >> 5, lane = tid & 31;
    for (int i = warp; i < 512; i += 16) {
        float acc = 0.f;
        const float* row = aw + (size_t)i * 512;
        for (int j = lane; j < 512; j += 32) acc += wsh[j] * row[j];
        #pragma unroll
        for (int off = 16; off; off >>= 1) acc += __shfl_down_sync(0xffffffffu, acc, off);
        if (lane == 0) g_styles[n * 512 + i] = acc * 0.04419417382415922f + ab[i];
    }
}

// ---------------- K2: s normalize ----------------
__global__ void k_snorm() {
    int tid = threadIdx.x;
    __shared__ float red[256];
    __shared__ float rstd_s;
    float a = 0.f;
    for (int idx = tid; idx < NB * CIN; idx += 256) { float v = g_styles[idx]; a += v * v; }
    red[tid] = a; __syncthreads();
    for (int off = 128; off; off >>= 1) { if (tid < off) red[tid] += red[tid + off]; __syncthreads(); }
    if (tid == 0) rstd_s = rsqrtf(red[0] / (float)(NB * CIN));
    __syncthreads();
    float rs = rstd_s;
    for (int idx = tid; idx < NB * CIN; idx += 256) g_s[idx] = g_styles[idx] * rs;
}

// ---------------- K3: rn, qraw, wth[kk][oc][i] fp16 ----------------
__global__ void k_rn(const float* __restrict__ cw) {
    int o = blockIdx.x, tid = threadIdx.x;
    const float* cwo = cw + (size_t)o * 4608;
    __shared__ float red[256];
    __shared__ float rn_s;
    float a = 0.f;
    for (int idx = tid; idx < 4608; idx += 256) { float v = cwo[idx]; a += v * v; }
    red[tid] = a; __syncthreads();
    for (int off = 128; off; off >>= 1) { if (tid < off) red[tid] += red[tid + off]; __syncthreads(); }
    if (tid == 0) { rn_s = rsqrtf(red[0] / 4608.f); g_rn[o] = rn_s; }
    __syncthreads();
    float rn = rn_s;
    for (int i = tid; i < 512; i += 256) {
        float q = 0.f;
        #pragma unroll
        for (int kk = 0; kk < 9; kk++) { float v = cwo[i * 9 + kk]; q += v * v; }
        g_qraw[o * 512 + i] = q;
    }
    #pragma unroll
    for (int kk = 0; kk < 9; kk++)
        for (int i = tid; i < 512; i += 256)
            g_wth[((size_t)(kk * 512) + o) * 512 + i] = __float2half(cwo[i * 9 + kk] * rn);
}

// ---------------- K4: d[n][o]  (grid 512, block 128) ----------------
__global__ void k_d() {
    int o = blockIdx.x, tid = threadIdx.x;
    int warp = tid >> 5, lane = tid & 31;
    __shared__ float qsh[512];
    for (int i = tid; i < 512; i += 128) qsh[i] = g_qraw[o * 512 + i];
    __syncthreads();
    float rn = g_rn[o];
    for (int n = warp; n < NB; n += 4) {
        float acc = 0.f;
        for (int i = lane; i < 512; i += 32) {
            float sv = g_s[n * 512 + i];
            acc += sv * sv * qsh[i];
        }
        #pragma unroll
        for (int off = 16; off; off >>= 1) acc += __shfl_down_sync(0xffffffffu, acc, off);
        if (lane == 0) g_d[n * 512 + o] = rsqrtf(rn * rn * acc + 1e-8f);
    }
}

// ---------------- K5: NHWC padded, scaled input fp16 ----------------
__global__ __launch_bounds__(512) void k_pad(const float* __restrict__ x) {
    int yy = blockIdx.x, n = blockIdx.y, tid = threadIdx.x;
    __shared__ float ts[128][65];
    __half* orow = g_xph + ((size_t)(n * 68 + yy) * 68) * 512;
    bool inner = (yy >= 2 && yy < 66);
    for (int ct = 0; ct < 4; ct++) {
        __syncthreads();
        if (inner) {
            #pragma unroll
            for (int it = 0; it < 16; it++) {
                int idx = it * 512 + tid;
                int c = idx >> 6, xx = idx & 63;
                int cg = ct * 128 + c;
                ts[c][xx] = x[(((size_t)(n * 512) + cg) * 64 + (yy - 2)) * 64 + xx] * g_s[n * 512 + cg];
            }
        }
        __syncthreads();
        #pragma unroll
        for (int it = 0; it < 9; it++) {
            int idx = it * 512 + tid;               // 68*64 = 4352 half2 items
            if (idx < 68 * 64) {
                int xx = idx >> 6, c2 = idx & 63;
                int c = c2 * 2;
                float v0 = 0.f, v1 = 0.f;
                if (inner && xx >= 2 && xx < 66) { v0 = ts[c][xx - 2]; v1 = ts[c + 1][xx - 2]; }
                *(__half2*)(orow + xx * 512 + ct * 128 + c) = __floats2half2_rn(v0, v1);
            }
        }
    }
}

// ---------------- K6: conv via mma.sync fp16 implicit GEMM ----------------
// CTA tile 128 oc x 128 px, warp tile 32x64 (4x2 warps). 3-stage, 2 CTA/SM.
#define STAGE_B 32768
__global__ __launch_bounds__(256, 2) void k_conv(const float* __restrict__ cbias) {
    extern __shared__ char smem[];
    uint32_t sb = smem_u32(smem);
    int tid = threadIdx.x, lane = tid & 31, wid = tid >> 5;
    int pt = blockIdx.x, ot = blockIdx.y, n = blockIdx.z;
    int p0 = pt * 128;
    int wm = wid & 3, wn = wid >> 2;

    float C[2][8][4];
    #pragma unroll
    for (int i = 0; i < 2; i++)
        #pragma unroll
        for (int j = 0; j < 8; j++)
            #pragma unroll
            for (int k = 0; k < 4; k++) C[i][j][k] = 0.f;

    int ch = tid & 7;
    int trow = tid >> 3;

    uint32_t browoff[4];
    #pragma unroll
    for (int b = 0; b < 4; b++) {
        int row = b * 32 + trow;
        int p = p0 + row; if (p > 4355) p = 4355;
        int y = p / 66, xx = p - y * 66;
        browoff[b] = ((uint32_t)(n * 68 + y) * 68 + xx) * 512;
    }
    uint32_t sA_st[4], sB_st[4];
    #pragma unroll
    for (int a = 0; a < 4; a++) sA_st[a] = swz(((a * 32 + trow) * 128) + ch * 16);
    #pragma unroll
    for (int b = 0; b < 4; b++) sB_st[b] = 16384 + swz(((b * 32 + trow) * 128) + ch * 16);

#define LOAD_TILE(js_, slot_) do { \
    int kk_ = (js_) >> 3; int i0_ = ((js_) & 7) << 6; \
    int ky_ = kk_ / 3, kx_ = kk_ - ky_ * 3; \
    uint32_t stb_ = sb + (uint32_t)(slot_) * STAGE_B; \
    const __half* ap_ = g_wth + ((size_t)(kk_ * 512 + ot * 128)) * 512 + i0_ + ch * 8; \
    _Pragma("unroll") \
    for (int a_ = 0; a_ < 4; a_++) { \
        uint32_t sa_ = stb_ + sA_st[a_]; \
        const __half* ga_ = ap_ + (size_t)(a_ * 32 + trow) * 512; \
        asm volatile("cp.async.cg.shared.global [%0], [%1], 16;" :: "r"(sa_), "l"(ga_)); \
    } \
    uint32_t koff_ = (uint32_t)(ky_ * 68 + kx_) * 512 + i0_ + ch * 8; \
    _Pragma("unroll") \
    for (int b_ = 0; b_ < 4; b_++) { \
        uint32_t sa_ = stb_ + sB_st[b_]; \
        const __half* gb_ = g_xph + browoff[b_] + koff_; \
        asm volatile("cp.async.cg.shared.global [%0], [%1], 16;" :: "r"(sa_), "l"(gb_)); \
    } \
    asm volatile("cp.async.commit_group;" ::: "memory"); \
} while (0)

    LOAD_TILE(0, 0);
    LOAD_TILE(1, 1);

    uint32_t aRow = wm * 32 + (lane & 15);
    uint32_t aCol = (uint32_t)(lane >> 4);
    uint32_t bRow = wn * 64 + ((lane >> 4) << 3) + (lane & 7);
    uint32_t bCol = (uint32_t)((lane >> 3) & 1);

    for (int js = 0; js < 72; js++) {
        int cur = js % 3;
        asm volatile("cp.async.wait_group 1;" ::: "memory");
        __syncthreads();
        if (js + 2 < 72) { LOAD_TILE(js + 2, (js + 2) % 3); }
        else { asm volatile("cp.async.commit_group;" ::: "memory"); }

        uint32_t sA = sb + (uint32_t)cur * STAGE_B;
        uint32_t sB = sA + 16384;
        #pragma unroll
        for (int ks = 0; ks < 4; ks++) {
            uint32_t af[2][4], bf[4][4];
            #pragma unroll
            for (int mt = 0; mt < 2; mt++)
                ldsm4(af[mt], sA + swz((aRow + mt * 16) * 128 + (ks * 2 + aCol) * 16));
            #pragma unroll
            for (int bt = 0; bt < 4; bt++)
                ldsm4(bf[bt], sB + swz((bRow + bt * 16) * 128 + (ks * 2 + bCol) * 16));
            #pragma unroll
            for (int mt = 0; mt < 2; mt++)
                #pragma unroll
                for (int bt = 0; bt < 4; bt++) {
                    mma16816(C[mt][2 * bt],     af[mt], bf[bt][0], bf[bt][1]);
                    mma16816(C[mt][2 * bt + 1], af[mt], bf[bt][2], bf[bt][3]);
                }
        }
    }

    // ---- epilogue: *d + bias -> g_y0h (fp16) ----
    int obase = ot * 128 + wm * 32;
    __half* y0n = g_y0h + (size_t)n * 512 * 4356;
    bool tail = (pt == 34);
    #pragma unroll
    for (int mt = 0; mt < 2; mt++) {
        int r0 = obase + mt * 16 + (lane >> 2);
        int r1 = r0 + 8;
        float d0 = g_d[n * 512 + r0], bb0 = cbias[r0];
        float d1 = g_d[n * 512 + r1], bb1 = cbias[r1];
        __half* row0 = y0n + (size_t)r0 * 4356;
        __half* row1 = y0n + (size_t)r1 * 4356;
        #pragma unroll
        for (int nt = 0; nt < 8; nt++) {
            int p = p0 + wn * 64 + nt * 8 + 2 * (lane & 3);
            if (!tail || p + 1 < 4356) {
                *(__half2*)(row0 + p) = __floats2half2_rn(C[mt][nt][0] * d0 + bb0, C[mt][nt][1] * d0 + bb0);
                *(__half2*)(row1 + p) = __floats2half2_rn(C[mt][nt][2] * d1 + bb1, C[mt][nt][3] * d1 + bb1);
            } else if (p < 4356) {
                row0[p] = __float2half(C[mt][nt][0] * d0 + bb0);
                row1[p] = __float2half(C[mt][nt][2] * d1 + bb1);
            }
        }
    }
}

// ---------------- K7: fused filtered_lrelu (paired-output, R3 layouts) ----------------
// A: SIN[76][68] then Z[138][140]; B: T1[138][76] then V[138][64]
__global__ __launch_bounds__(512) void k_flrelu(const float* __restrict__ uf,
                                                const float* __restrict__ dfl,
                                                float* __restrict__ out) {
    extern __shared__ float sm[];
    float* A = sm;
    float* B = sm + 19320;
    __shared__ float fs[12], ds[12];

    int tid = threadIdx.x;
    if (tid < 12) fs[tid] = uf[tid];
    else if (tid < 24) ds[tid - 12] = dfl[tid - 12];

    const __half* img = g_y0h + (size_t)blockIdx.x * (66 * 66);

    // P0: SIN (rows 5..70 data) + zero T1 border cols 0..4, 71..75
    for (int idx = tid; idx < 76 * 68; idx += 512) {
        int row = idx / 68, col = idx - row * 68;
        int ry = row - 5;
        float v = 0.f;
        if (ry >= 0 && ry < 66 && col < 66) v = __half2float(img[ry * 66 + col]);
        A[idx] = v;
    }
    for (int idx = tid; idx < 138 * 10; idx += 512) {
        int r = idx / 10, c = idx - r * 10;
        B[r * 76 + (c < 5 ? c : 66 + c)] = 0.f;
    }
    __syncthreads();

    // P1: vertical up-FIR, paired rows (2m, 2m+1) share A rows m+1..m+6
    for (int idx = tid; idx < 69 * 66; idx += 512) {
        int m = idx / 66, x = idx - m * 66;
        float av[6];
        #pragma unroll
        for (int k = 0; k < 6; k++) av[k] = A[(m + 1 + k) * 68 + x];
        float se = 0.f, so = 0.f;
        #pragma unroll
        for (int k = 0; k < 6; k++) {
            se += fs[1 + 2 * k] * av[k];
            so += fs[2 * k]     * av[k];
        }
        B[(2 * m) * 76 + x + 5]     = se;
        B[(2 * m + 1) * 76 + x + 5] = so;
    }
    __syncthreads();

    // P2: horizontal up-FIR + gain4 + lrelu*sqrt2 + clamp, paired cols (2m, 2m+1)
    for (int idx = tid; idx < 138 * 69; idx += 512) {
        int uy = idx / 69, m = idx - uy * 69;
        float tv[6];
        #pragma unroll
        for (int k = 0; k < 6; k++) tv[k] = B[uy * 76 + m + 1 + k];
        float ze = 0.f, zo = 0.f;
        #pragma unroll
        for (int k = 0; k < 6; k++) {
            ze += fs[1 + 2 * k] * tv[k];
            zo += fs[2 * k]     * tv[k];
        }
        ze *= 4.f; zo *= 4.f;
        ze = (ze >= 0.f ? ze : 0.2f * ze) * 1.4142135623730951f;
        zo = (zo >= 0.f ? zo : 0.2f * zo) * 1.4142135623730951f;
        ze = fminf(fmaxf(ze, -256.f), 256.f);
        zo = fminf(fmaxf(zo, -256.f), 256.f);
        *(float2*)&A[uy * 140 + 2 * m] = make_float2(ze, zo);
    }
    __syncthreads();

    // P3: horizontal down-FIR with float2 reads -> V[uy][ox] in B
    for (int idx = tid; idx < 138 * 64; idx += 512) {
        int uy = idx >> 6, ox = idx & 63;
        float acc = 0.f;
        #pragma unroll
        for (int t2 = 0; t2 < 6; t2++) {
            float2 z2 = *(const float2*)&A[uy * 140 + 2 * ox + 2 * t2];
            acc += ds[2 * t2] * z2.x + ds[2 * t2 + 1] * z2.y;
        }
        B[uy * 64 + ox] = acc;
    }
    __syncthreads();

    // P4: vertical down-FIR, 4 outputs per thread share 18 row-reads
    float* o = out + (size_t)blockIdx.x * (64 * 64);
    #pragma unroll
    for (int idx = tid; idx < 1024; idx += 512) {
        int strip = idx >> 6, ox = idx & 63;
        int oy0 = strip * 4;
        float vv[18];
        #pragma unroll
        for (int j = 0; j < 18; j++) vv[j] = B[(2 * oy0 + j) * 64 + ox];
        #pragma unroll
        for (int p = 0; p < 4; p++) {
            float acc = 0.f;
            #pragma unroll
            for (int t = 0; t < 12; t++) acc += ds[t] * vv[2 * p + t];
            o[(oy0 + p) * 64 + ox] = acc;
        }
    }
}

// ---------------- launch ----------------
extern "C" void kernel_launch(void* const* d_in, const int* in_sizes, int n_in,
                              void* d_out, int out_size) {
    const float* x  = (const float*)d_in[0];
    const float* w  = (const float*)d_in[1];
    const float* aw = (const float*)d_in[2];
    const float* ab = (const float*)d_in[3];
    const float* cw = (const float*)d_in[4];
    const float* cb = (const float*)d_in[5];
    const float* uf = (const float*)d_in[6];
    const float* df = (const float*)d_in[7];
    float* out = (float*)d_out;
    (void)in_sizes; (void)n_in; (void)out_size;

    cudaFuncSetAttribute(k_conv,   cudaFuncAttributeMaxDynamicSharedMemorySize, 3 * STAGE_B);
    cudaFuncSetAttribute(k_flrelu, cudaFuncAttributeMaxDynamicSharedMemorySize, 119232);

    k_styles<<<NB, 512>>>(w, aw, ab);
    k_snorm<<<1, 256>>>();
    k_rn<<<COUT, 256>>>(cw);
    k_d<<<COUT, 128>>>();
    k_pad<<<dim3(68, NB), 512>>>(x);
    k_conv<<<dim3(35, 4, NB), 256, 3 * STAGE_B>>>(cb);
    k_flrelu<<<NB * COUT, 512, 119232>>>(uf, df, out);
}

// round 12
// speedup vs baseline: 1.8085x; 1.1879x over previous
#include <cuda_runtime.h>
#include <cuda_fp16.h>
#include <cstdint>

#define NB   16
#define CIN  512
#define COUT 512
#define RES  64

// ---------------- device scratch ----------------
__device__ float  g_styles[NB * CIN];
__device__ float  g_s[NB * CIN];
__device__ float  g_rn[COUT];
__device__ float  g_qraw[COUT * CIN];
__device__ float  g_d[NB * COUT];
__device__ __half g_wth[9 * COUT * CIN];            // [kk][oc][i] fp16
__device__ __half g_xph[NB * 68 * 68 * CIN];        // NHWC padded, style-scaled fp16
__device__ __half g_y0h[NB * COUT * 66 * 66];       // conv out (+d, +bias) fp16

// ---------------- helpers ----------------
__device__ __forceinline__ uint32_t smem_u32(const void* p) {
    uint32_t a;
    asm("{ .reg .u64 t; cvta.to.shared.u64 t, %1; cvt.u32.u64 %0, t; }" : "=r"(a) : "l"(p));
    return a;
}
__device__ __forceinline__ uint32_t swz(uint32_t o) { return o ^ ((o >> 3) & 0x70); }

__device__ __forceinline__ void ldsm4(uint32_t* r, uint32_t addr) {
    asm volatile("ldmatrix.sync.aligned.m8n8.x4.shared.b16 {%0,%1,%2,%3}, [%4];"
        : "=r"(r[0]), "=r"(r[1]), "=r"(r[2]), "=r"(r[3]) : "r"(addr));
}
__device__ __forceinline__ void mma16816(float* c, const uint32_t* a, uint32_t b0, uint32_t b1) {
    asm volatile("mma.sync.aligned.m16n8k16.row.col.f32.f16.f16.f32 "
        "{%0,%1,%2,%3}, {%4,%5,%6,%7}, {%8,%9}, {%0,%1,%2,%3};"
        : "+f"(c[0]), "+f"(c[1]), "+f"(c[2]), "+f"(c[3])
        : "r"(a[0]), "r"(a[1]), "r"(a[2]), "r"(a[3]), "r"(b0), "r"(b1));
}

// ---------------- K1: styles ----------------
__global__ void k_styles(const float* __restrict__ w,
                         const float* __restrict__ aw,
                         const float* __restrict__ ab) {
    int n = blockIdx.x, tid = threadIdx.x;
    __shared__ float wsh[512];
    wsh[tid] = w[n * 512 + tid];
    __syncthreads();
    int warp = tid >> 5, lane = tid & 31;
    for (int i = warp; i < 512; i += 16) {
        float acc = 0.f;
        const float* row = aw + (size_t)i * 512;
        for (int j = lane; j < 512; j += 32) acc += wsh[j] * row[j];
        #pragma unroll
        for (int off = 16; off; off >>= 1) acc += __shfl_down_sync(0xffffffffu, acc, off);
        if (lane == 0) g_styles[n * 512 + i] = acc * 0.04419417382415922f + ab[i];
    }
}

// ---------------- K2: s normalize ----------------
__global__ void k_snorm() {
    int tid = threadIdx.x;
    __shared__ float red[256];
    __shared__ float rstd_s;
    float a = 0.f;
    for (int idx = tid; idx < NB * CIN; idx += 256) { float v = g_styles[idx]; a += v * v; }
    red[tid] = a; __syncthreads();
    for (int off = 128; off; off >>= 1) { if (tid < off) red[tid] += red[tid + off]; __syncthreads(); }
    if (tid == 0) rstd_s = rsqrtf(red[0] / (float)(NB * CIN));
    __syncthreads();
    float rs = rstd_s;
    for (int idx = tid; idx < NB * CIN; idx += 256) g_s[idx] = g_styles[idx] * rs;
}

// ---------------- K3: rn, qraw, wth (weight row cached in smem) ----------------
__global__ void k_rn(const float* __restrict__ cw) {
    int o = blockIdx.x, tid = threadIdx.x;
    const float* cwo = cw + (size_t)o * 4608;
    __shared__ float wsh[4608];
    __shared__ float red[256];
    __shared__ float rn_s;
    float a = 0.f;
    for (int idx = tid; idx < 4608; idx += 256) {
        float v = cwo[idx];
        wsh[idx] = v;
        a += v * v;
    }
    red[tid] = a; __syncthreads();
    for (int off = 128; off; off >>= 1) { if (tid < off) red[tid] += red[tid + off]; __syncthreads(); }
    if (tid == 0) { rn_s = rsqrtf(red[0] / 4608.f); g_rn[o] = rn_s; }
    __syncthreads();
    float rn = rn_s;
    for (int i = tid; i < 512; i += 256) {
        float q = 0.f;
        #pragma unroll
        for (int kk = 0; kk < 9; kk++) { float v = wsh[i * 9 + kk]; q += v * v; }
        g_qraw[o * 512 + i] = q;
    }
    #pragma unroll
    for (int kk = 0; kk < 9; kk++)
        for (int i = tid; i < 512; i += 256)
            g_wth[((size_t)(kk * 512) + o) * 512 + i] = __float2half(wsh[i * 9 + kk] * rn);
}

// ---------------- K4: d[n][o]  (grid 512, block 128) ----------------
__global__ void k_d() {
    int o = blockIdx.x, tid = threadIdx.x;
    int warp = tid >> 5, lane = tid & 31;
    __shared__ float qsh[512];
    for (int i = tid; i < 512; i += 128) qsh[i] = g_qraw[o * 512 + i];
    __syncthreads();
    float rn = g_rn[o];
    for (int n = warp; n < NB; n += 4) {
        float acc = 0.f;
        for (int i = lane; i < 512; i += 32) {
            float sv = g_s[n * 512 + i];
            acc += sv * sv * qsh[i];
        }
        #pragma unroll
        for (int off = 16; off; off >>= 1) acc += __shfl_down_sync(0xffffffffu, acc, off);
        if (lane == 0) g_d[n * 512 + o] = rsqrtf(rn * rn * acc + 1e-8f);
    }
}

// ---------------- K5: NHWC padded, scaled input fp16 ----------------
__global__ __launch_bounds__(512) void k_pad(const float* __restrict__ x) {
    int yy = blockIdx.x, n = blockIdx.y, tid = threadIdx.x;
    __shared__ float ts[128][65];
    __half* orow = g_xph + ((size_t)(n * 68 + yy) * 68) * 512;
    bool inner = (yy >= 2 && yy < 66);
    for (int ct = 0; ct < 4; ct++) {
        __syncthreads();
        if (inner) {
            #pragma unroll
            for (int it = 0; it < 16; it++) {
                int idx = it * 512 + tid;
                int c = idx >> 6, xx = idx & 63;
                int cg = ct * 128 + c;
                ts[c][xx] = x[(((size_t)(n * 512) + cg) * 64 + (yy - 2)) * 64 + xx] * g_s[n * 512 + cg];
            }
        }
        __syncthreads();
        #pragma unroll
        for (int it = 0; it < 9; it++) {
            int idx = it * 512 + tid;
            if (idx < 68 * 64) {
                int xx = idx >> 6, c2 = idx & 63;
                int c = c2 * 2;
                float v0 = 0.f, v1 = 0.f;
                if (inner && xx >= 2 && xx < 66) { v0 = ts[c][xx - 2]; v1 = ts[c + 1][xx - 2]; }
                *(__half2*)(orow + xx * 512 + ct * 128 + c) = __floats2half2_rn(v0, v1);
            }
        }
    }
}

// ---------------- K6: conv via mma.sync fp16 implicit GEMM ----------------
#define STAGE_B 32768
__global__ __launch_bounds__(256, 2) void k_conv(const float* __restrict__ cbias) {
    extern __shared__ char smem[];
    uint32_t sb = smem_u32(smem);
    int tid = threadIdx.x, lane = tid & 31, wid = tid >> 5;
    int pt = blockIdx.x, ot = blockIdx.y, n = blockIdx.z;
    int p0 = pt * 128;
    int wm = wid & 3, wn = wid >> 2;

    float C[2][8][4];
    #pragma unroll
    for (int i = 0; i < 2; i++)
        #pragma unroll
        for (int j = 0; j < 8; j++)
            #pragma unroll
            for (int k = 0; k < 4; k++) C[i][j][k] = 0.f;

    int ch = tid & 7;
    int trow = tid >> 3;

    uint32_t browoff[4];
    #pragma unroll
    for (int b = 0; b < 4; b++) {
        int row = b * 32 + trow;
        int p = p0 + row; if (p > 4355) p = 4355;
        int y = p / 66, xx = p - y * 66;
        browoff[b] = ((uint32_t)(n * 68 + y) * 68 + xx) * 512;
    }
    uint32_t sA_st[4], sB_st[4];
    #pragma unroll
    for (int a = 0; a < 4; a++) sA_st[a] = swz(((a * 32 + trow) * 128) + ch * 16);
    #pragma unroll
    for (int b = 0; b < 4; b++) sB_st[b] = 16384 + swz(((b * 32 + trow) * 128) + ch * 16);

#define LOAD_TILE(js_, slot_) do { \
    int kk_ = (js_) >> 3; int i0_ = ((js_) & 7) << 6; \
    int ky_ = kk_ / 3, kx_ = kk_ - ky_ * 3; \
    uint32_t stb_ = sb + (uint32_t)(slot_) * STAGE_B; \
    const __half* ap_ = g_wth + ((size_t)(kk_ * 512 + ot * 128)) * 512 + i0_ + ch * 8; \
    _Pragma("unroll") \
    for (int a_ = 0; a_ < 4; a_++) { \
        uint32_t sa_ = stb_ + sA_st[a_]; \
        const __half* ga_ = ap_ + (size_t)(a_ * 32 + trow) * 512; \
        asm volatile("cp.async.cg.shared.global [%0], [%1], 16;" :: "r"(sa_), "l"(ga_)); \
    } \
    uint32_t koff_ = (uint32_t)(ky_ * 68 + kx_) * 512 + i0_ + ch * 8; \
    _Pragma("unroll") \
    for (int b_ = 0; b_ < 4; b_++) { \
        uint32_t sa_ = stb_ + sB_st[b_]; \
        const __half* gb_ = g_xph + browoff[b_] + koff_; \
        asm volatile("cp.async.cg.shared.global [%0], [%1], 16;" :: "r"(sa_), "l"(gb_)); \
    } \
    asm volatile("cp.async.commit_group;" ::: "memory"); \
} while (0)

    LOAD_TILE(0, 0);
    LOAD_TILE(1, 1);

    uint32_t aRow = wm * 32 + (lane & 15);
    uint32_t aCol = (uint32_t)(lane >> 4);
    uint32_t bRow = wn * 64 + ((lane >> 4) << 3) + (lane & 7);
    uint32_t bCol = (uint32_t)((lane >> 3) & 1);

    for (int js = 0; js < 72; js++) {
        int cur = js % 3;
        asm volatile("cp.async.wait_group 1;" ::: "memory");
        __syncthreads();
        if (js + 2 < 72) { LOAD_TILE(js + 2, (js + 2) % 3); }
        else { asm volatile("cp.async.commit_group;" ::: "memory"); }

        uint32_t sA = sb + (uint32_t)cur * STAGE_B;
        uint32_t sB = sA + 16384;
        #pragma unroll
        for (int ks = 0; ks < 4; ks++) {
            uint32_t af[2][4], bf[4][4];
            #pragma unroll
            for (int mt = 0; mt < 2; mt++)
                ldsm4(af[mt], sA + swz((aRow + mt * 16) * 128 + (ks * 2 + aCol) * 16));
            #pragma unroll
            for (int bt = 0; bt < 4; bt++)
                ldsm4(bf[bt], sB + swz((bRow + bt * 16) * 128 + (ks * 2 + bCol) * 16));
            #pragma unroll
            for (int mt = 0; mt < 2; mt++)
                #pragma unroll
                for (int bt = 0; bt < 4; bt++) {
                    mma16816(C[mt][2 * bt],     af[mt], bf[bt][0], bf[bt][1]);
                    mma16816(C[mt][2 * bt + 1], af[mt], bf[bt][2], bf[bt][3]);
                }
        }
    }

    // ---- epilogue: *d + bias -> g_y0h (fp16) ----
    int obase = ot * 128 + wm * 32;
    __half* y0n = g_y0h + (size_t)n * 512 * 4356;
    bool tail = (pt == 34);
    #pragma unroll
    for (int mt = 0; mt < 2; mt++) {
        int r0 = obase + mt * 16 + (lane >> 2);
        int r1 = r0 + 8;
        float d0 = g_d[n * 512 + r0], bb0 = cbias[r0];
        float d1 = g_d[n * 512 + r1], bb1 = cbias[r1];
        __half* row0 = y0n + (size_t)r0 * 4356;
        __half* row1 = y0n + (size_t)r1 * 4356;
        #pragma unroll
        for (int nt = 0; nt < 8; nt++) {
            int p = p0 + wn * 64 + nt * 8 + 2 * (lane & 3);
            if (!tail || p + 1 < 4356) {
                *(__half2*)(row0 + p) = __floats2half2_rn(C[mt][nt][0] * d0 + bb0, C[mt][nt][1] * d0 + bb0);
                *(__half2*)(row1 + p) = __floats2half2_rn(C[mt][nt][2] * d1 + bb1, C[mt][nt][3] * d1 + bb1);
            } else if (p < 4356) {
                row0[p] = __float2half(C[mt][nt][0] * d0 + bb0);
                row1[p] = __float2half(C[mt][nt][2] * d1 + bb1);
            }
        }
    }
}

// ---------------- K7: fused filtered_lrelu (fp16 intermediates, 3 blocks/SM) ----------------
// Region A (offset 0):    SIN fp32[76][68] (20672B)  then  Z __half[138][140] (38640B)
// Region B (offset 38656): T1 __half[138][80] (22080B) then V fp32[138][64] (35328B)
#define FL_B_OFF 38656
#define FL_SMEM  (FL_B_OFF + 35328)
__global__ __launch_bounds__(512) void k_flrelu(const float* __restrict__ uf,
                                                const float* __restrict__ dfl,
                                                float* __restrict__ out) {
    extern __shared__ char smc[];
    float*  SIN = (float*)smc;
    __half* Z   = (__half*)smc;
    __half* T1  = (__half*)(smc + FL_B_OFF);
    float*  V   = (float*)(smc + FL_B_OFF);
    __shared__ float fs[12], ds[12];

    int tid = threadIdx.x;
    if (tid < 12) fs[tid] = uf[tid];
    else if (tid < 24) ds[tid - 12] = dfl[tid - 12];

    const __half* img = g_y0h + (size_t)blockIdx.x * (66 * 66);

    // P0: SIN load + zero entire T1 region (covers border columns)
    for (int idx = tid; idx < 76 * 68; idx += 512) {
        int row = idx / 68, col = idx - row * 68;
        int ry = row - 5;
        float v = 0.f;
        if (ry >= 0 && ry < 66 && col < 66) v = __half2float(img[ry * 66 + col]);
        SIN[idx] = v;
    }
    for (int idx = tid; idx < (138 * 80) / 2; idx += 512)
        ((uint32_t*)T1)[idx] = 0u;
    __syncthreads();

    // P1: vertical up-FIR, paired rows (2m, 2m+1) share SIN rows m+1..m+6
    for (int idx = tid; idx < 69 * 66; idx += 512) {
        int m = idx / 66, x = idx - m * 66;
        float av[6];
        #pragma unroll
        for (int k = 0; k < 6; k++) av[k] = SIN[(m + 1 + k) * 68 + x];
        float se = 0.f, so = 0.f;
        #pragma unroll
        for (int k = 0; k < 6; k++) {
            se += fs[1 + 2 * k] * av[k];
            so += fs[2 * k]     * av[k];
        }
        T1[(2 * m) * 80 + x + 5]     = __float2half(se);
        T1[(2 * m + 1) * 80 + x + 5] = __float2half(so);
    }
    __syncthreads();

    // P2: horizontal up-FIR + gain4 + lrelu*sqrt2 + clamp -> Z half2 (overwrites SIN)
    for (int idx = tid; idx < 138 * 69; idx += 512) {
        int uy = idx / 69, m = idx - uy * 69;
        float tv[6];
        #pragma unroll
        for (int k = 0; k < 6; k++) tv[k] = __half2float(T1[uy * 80 + m + 1 + k]);
        float ze = 0.f, zo = 0.f;
        #pragma unroll
        for (int k = 0; k < 6; k++) {
            ze += fs[1 + 2 * k] * tv[k];
            zo += fs[2 * k]     * tv[k];
        }
        ze *= 4.f; zo *= 4.f;
        ze = (ze >= 0.f ? ze : 0.2f * ze) * 1.4142135623730951f;
        zo = (zo >= 0.f ? zo : 0.2f * zo) * 1.4142135623730951f;
        ze = fminf(fmaxf(ze, -256.f), 256.f);
        zo = fminf(fmaxf(zo, -256.f), 256.f);
        *(__half2*)&Z[uy * 140 + 2 * m] = __floats2half2_rn(ze, zo);
    }
    __syncthreads();

    // P3: horizontal down-FIR (half2 reads) -> V fp32 (overwrites T1)
    for (int idx = tid; idx < 138 * 64; idx += 512) {
        int uy = idx >> 6, ox = idx & 63;
        float acc = 0.f;
        #pragma unroll
        for (int t2 = 0; t2 < 6; t2++) {
            float2 z2 = __half22float2(*(const __half2*)&Z[uy * 140 + 2 * ox + 2 * t2]);
            acc += ds[2 * t2] * z2.x + ds[2 * t2 + 1] * z2.y;
        }
        V[uy * 64 + ox] = acc;
    }
    __syncthreads();

    // P4: vertical down-FIR, 4 outputs per thread share 18 row-reads
    float* o = out + (size_t)blockIdx.x * (64 * 64);
    #pragma unroll
    for (int idx = tid; idx < 1024; idx += 512) {
        int strip = idx >> 6, ox = idx & 63;
        int oy0 = strip * 4;
        float vv[18];
        #pragma unroll
        for (int j = 0; j < 18; j++) vv[j] = V[(2 * oy0 + j) * 64 + ox];
        #pragma unroll
        for (int p = 0; p < 4; p++) {
            float acc = 0.f;
            #pragma unroll
            for (int t = 0; t < 12; t++) acc += ds[t] * vv[2 * p + t];
            o[(oy0 + p) * 64 + ox] = acc;
        }
    }
}

// ---------------- launch ----------------
extern "C" void kernel_launch(void* const* d_in, const int* in_sizes, int n_in,
                              void* d_out, int out_size) {
    const float* x  = (const float*)d_in[0];
    const float* w  = (const float*)d_in[1];
    const float* aw = (const float*)d_in[2];
    const float* ab = (const float*)d_in[3];
    const float* cw = (const float*)d_in[4];
    const float* cb = (const float*)d_in[5];
    const float* uf = (const float*)d_in[6];
    const float* df = (const float*)d_in[7];
    float* out = (float*)d_out;
    (void)in_sizes; (void)n_in; (void)out_size;

    cudaFuncSetAttribute(k_conv,   cudaFuncAttributeMaxDynamicSharedMemorySize, 3 * STAGE_B);
    cudaFuncSetAttribute(k_flrelu, cudaFuncAttributeMaxDynamicSharedMemorySize, FL_SMEM);

    k_styles<<<NB, 512>>>(w, aw, ab);
    k_snorm<<<1, 256>>>();
    k_rn<<<COUT, 256>>>(cw);
    k_d<<<COUT, 128>>>();
    k_pad<<<dim3(68, NB), 512>>>(x);
    k_conv<<<dim3(35, 4, NB), 256, 3 * STAGE_B>>>(cb);
    k_flrelu<<<NB * COUT, 512, FL_SMEM>>>(uf, df, out);
}

// round 13
// speedup vs baseline: 1.9960x; 1.1037x over previous
#include <cuda_runtime.h>
#include <cuda_fp16.h>
#include <cstdint>

#define NB   16
#define CIN  512
#define COUT 512
#define RES  64

// ---------------- device scratch ----------------
__device__ float  g_styles[NB * CIN];
__device__ float  g_s[NB * CIN];
__device__ float  g_rn[COUT];
__device__ float  g_qraw[COUT * CIN];
__device__ float  g_d[NB * COUT];
__device__ __half g_wth[9 * COUT * CIN];            // [kk][oc][i] fp16
__device__ __half g_xph[NB * 68 * 68 * CIN];        // NHWC padded, style-scaled fp16
__device__ __half g_y0h[NB * COUT * 66 * 66];       // conv out (+d, +bias) fp16

// ---------------- helpers ----------------
__device__ __forceinline__ uint32_t smem_u32(const void* p) {
    uint32_t a;
    asm("{ .reg .u64 t; cvta.to.shared.u64 t, %1; cvt.u32.u64 %0, t; }" : "=r"(a) : "l"(p));
    return a;
}
__device__ __forceinline__ uint32_t swz(uint32_t o) { return o ^ ((o >> 3) & 0x70); }

__device__ __forceinline__ void ldsm4(uint32_t* r, uint32_t addr) {
    asm volatile("ldmatrix.sync.aligned.m8n8.x4.shared.b16 {%0,%1,%2,%3}, [%4];"
        : "=r"(r[0]), "=r"(r[1]), "=r"(r[2]), "=r"(r[3]) : "r"(addr));
}
__device__ __forceinline__ void mma16816(float* c, const uint32_t* a, uint32_t b0, uint32_t b1) {
    asm volatile("mma.sync.aligned.m16n8k16.row.col.f32.f16.f16.f32 "
        "{%0,%1,%2,%3}, {%4,%5,%6,%7}, {%8,%9}, {%0,%1,%2,%3};"
        : "+f"(c[0]), "+f"(c[1]), "+f"(c[2]), "+f"(c[3])
        : "r"(a[0]), "r"(a[1]), "r"(a[2]), "r"(a[3]), "r"(b0), "r"(b1));
}

// ---------------- K1: styles ----------------
__global__ void k_styles(const float* __restrict__ w,
                         const float* __restrict__ aw,
                         const float* __restrict__ ab) {
    int n = blockIdx.x, tid = threadIdx.x;
    __shared__ float wsh[512];
    wsh[tid] = w[n * 512 + tid];
    __syncthreads();
    int warp = tid >> 5, lane = tid & 31;
    for (int i = warp; i < 512; i += 16) {
        float acc = 0.f;
        const float* row = aw + (size_t)i * 512;
        for (int j = lane; j < 512; j += 32) acc += wsh[j] * row[j];
        #pragma unroll
        for (int off = 16; off; off >>= 1) acc += __shfl_down_sync(0xffffffffu, acc, off);
        if (lane == 0) g_styles[n * 512 + i] = acc * 0.04419417382415922f + ab[i];
    }
}

// ---------------- K2: s normalize ----------------
__global__ void k_snorm() {
    int tid = threadIdx.x;
    __shared__ float red[256];
    __shared__ float rstd_s;
    float a = 0.f;
    for (int idx = tid; idx < NB * CIN; idx += 256) { float v = g_styles[idx]; a += v * v; }
    red[tid] = a; __syncthreads();
    for (int off = 128; off; off >>= 1) { if (tid < off) red[tid] += red[tid + off]; __syncthreads(); }
    if (tid == 0) rstd_s = rsqrtf(red[0] / (float)(NB * CIN));
    __syncthreads();
    float rs = rstd_s;
    for (int idx = tid; idx < NB * CIN; idx += 256) g_s[idx] = g_styles[idx] * rs;
}

// ---------------- K3: rn, qraw, wth (weight row cached in smem) ----------------
__global__ void k_rn(const float* __restrict__ cw) {
    int o = blockIdx.x, tid = threadIdx.x;
    const float* cwo = cw + (size_t)o * 4608;
    __shared__ float wsh[4608];
    __shared__ float red[256];
    __shared__ float rn_s;
    float a = 0.f;
    for (int idx = tid; idx < 4608; idx += 256) {
        float v = cwo[idx];
        wsh[idx] = v;
        a += v * v;
    }
    red[tid] = a; __syncthreads();
    for (int off = 128; off; off >>= 1) { if (tid < off) red[tid] += red[tid + off]; __syncthreads(); }
    if (tid == 0) { rn_s = rsqrtf(red[0] / 4608.f); g_rn[o] = rn_s; }
    __syncthreads();
    float rn = rn_s;
    for (int i = tid; i < 512; i += 256) {
        float q = 0.f;
        #pragma unroll
        for (int kk = 0; kk < 9; kk++) { float v = wsh[i * 9 + kk]; q += v * v; }
        g_qraw[o * 512 + i] = q;
    }
    #pragma unroll
    for (int kk = 0; kk < 9; kk++)
        for (int i = tid; i < 512; i += 256)
            g_wth[((size_t)(kk * 512) + o) * 512 + i] = __float2half(wsh[i * 9 + kk] * rn);
}

// ---------------- K4: d[n][o]  (grid 512, block 128) ----------------
__global__ void k_d() {
    int o = blockIdx.x, tid = threadIdx.x;
    int warp = tid >> 5, lane = tid & 31;
    __shared__ float qsh[512];
    for (int i = tid; i < 512; i += 128) qsh[i] = g_qraw[o * 512 + i];
    __syncthreads();
    float rn = g_rn[o];
    for (int n = warp; n < NB; n += 4) {
        float acc = 0.f;
        for (int i = lane; i < 512; i += 32) {
            float sv = g_s[n * 512 + i];
            acc += sv * sv * qsh[i];
        }
        #pragma unroll
        for (int off = 16; off; off >>= 1) acc += __shfl_down_sync(0xffffffffu, acc, off);
        if (lane == 0) g_d[n * 512 + o] = rsqrtf(rn * rn * acc + 1e-8f);
    }
}

// ---------------- K5: NHWC padded, scaled input fp16 ----------------
__global__ __launch_bounds__(512) void k_pad(const float* __restrict__ x) {
    int yy = blockIdx.x, n = blockIdx.y, tid = threadIdx.x;
    __shared__ float ts[128][65];
    __half* orow = g_xph + ((size_t)(n * 68 + yy) * 68) * 512;
    bool inner = (yy >= 2 && yy < 66);
    for (int ct = 0; ct < 4; ct++) {
        __syncthreads();
        if (inner) {
            #pragma unroll
            for (int it = 0; it < 16; it++) {
                int idx = it * 512 + tid;
                int c = idx >> 6, xx = idx & 63;
                int cg = ct * 128 + c;
                ts[c][xx] = x[(((size_t)(n * 512) + cg) * 64 + (yy - 2)) * 64 + xx] * g_s[n * 512 + cg];
            }
        }
        __syncthreads();
        #pragma unroll
        for (int it = 0; it < 9; it++) {
            int idx = it * 512 + tid;
            if (idx < 68 * 64) {
                int xx = idx >> 6, c2 = idx & 63;
                int c = c2 * 2;
                float v0 = 0.f, v1 = 0.f;
                if (inner && xx >= 2 && xx < 66) { v0 = ts[c][xx - 2]; v1 = ts[c + 1][xx - 2]; }
                *(__half2*)(orow + xx * 512 + ct * 128 + c) = __floats2half2_rn(v0, v1);
            }
        }
    }
}

// ---------------- K6: conv via mma.sync fp16 implicit GEMM ----------------
#define STAGE_B 32768
__global__ __launch_bounds__(256, 2) void k_conv(const float* __restrict__ cbias) {
    extern __shared__ char smem[];
    uint32_t sb = smem_u32(smem);
    int tid = threadIdx.x, lane = tid & 31, wid = tid >> 5;
    int pt = blockIdx.x, ot = blockIdx.y, n = blockIdx.z;
    int p0 = pt * 128;
    int wm = wid & 3, wn = wid >> 2;

    float C[2][8][4];
    #pragma unroll
    for (int i = 0; i < 2; i++)
        #pragma unroll
        for (int j = 0; j < 8; j++)
            #pragma unroll
            for (int k = 0; k < 4; k++) C[i][j][k] = 0.f;

    int ch = tid & 7;
    int trow = tid >> 3;

    uint32_t browoff[4];
    #pragma unroll
    for (int b = 0; b < 4; b++) {
        int row = b * 32 + trow;
        int p = p0 + row; if (p > 4355) p = 4355;
        int y = p / 66, xx = p - y * 66;
        browoff[b] = ((uint32_t)(n * 68 + y) * 68 + xx) * 512;
    }
    uint32_t sA_st[4], sB_st[4];
    #pragma unroll
    for (int a = 0; a < 4; a++) sA_st[a] = swz(((a * 32 + trow) * 128) + ch * 16);
    #pragma unroll
    for (int b = 0; b < 4; b++) sB_st[b] = 16384 + swz(((b * 32 + trow) * 128) + ch * 16);

#define LOAD_TILE(js_, slot_) do { \
    int kk_ = (js_) >> 3; int i0_ = ((js_) & 7) << 6; \
    int ky_ = kk_ / 3, kx_ = kk_ - ky_ * 3; \
    uint32_t stb_ = sb + (uint32_t)(slot_) * STAGE_B; \
    const __half* ap_ = g_wth + ((size_t)(kk_ * 512 + ot * 128)) * 512 + i0_ + ch * 8; \
    _Pragma("unroll") \
    for (int a_ = 0; a_ < 4; a_++) { \
        uint32_t sa_ = stb_ + sA_st[a_]; \
        const __half* ga_ = ap_ + (size_t)(a_ * 32 + trow) * 512; \
        asm volatile("cp.async.cg.shared.global [%0], [%1], 16;" :: "r"(sa_), "l"(ga_)); \
    } \
    uint32_t koff_ = (uint32_t)(ky_ * 68 + kx_) * 512 + i0_ + ch * 8; \
    _Pragma("unroll") \
    for (int b_ = 0; b_ < 4; b_++) { \
        uint32_t sa_ = stb_ + sB_st[b_]; \
        const __half* gb_ = g_xph + browoff[b_] + koff_; \
        asm volatile("cp.async.cg.shared.global [%0], [%1], 16;" :: "r"(sa_), "l"(gb_)); \
    } \
    asm volatile("cp.async.commit_group;" ::: "memory"); \
} while (0)

    LOAD_TILE(0, 0);
    LOAD_TILE(1, 1);

    uint32_t aRow = wm * 32 + (lane & 15);
    uint32_t aCol = (uint32_t)(lane >> 4);
    uint32_t bRow = wn * 64 + ((lane >> 4) << 3) + (lane & 7);
    uint32_t bCol = (uint32_t)((lane >> 3) & 1);

    for (int js = 0; js < 72; js++) {
        int cur = js % 3;
        asm volatile("cp.async.wait_group 1;" ::: "memory");
        __syncthreads();
        if (js + 2 < 72) { LOAD_TILE(js + 2, (js + 2) % 3); }
        else { asm volatile("cp.async.commit_group;" ::: "memory"); }

        uint32_t sA = sb + (uint32_t)cur * STAGE_B;
        uint32_t sB = sA + 16384;
        #pragma unroll
        for (int ks = 0; ks < 4; ks++) {
            uint32_t af[2][4], bf[4][4];
            #pragma unroll
            for (int mt = 0; mt < 2; mt++)
                ldsm4(af[mt], sA + swz((aRow + mt * 16) * 128 + (ks * 2 + aCol) * 16));
            #pragma unroll
            for (int bt = 0; bt < 4; bt++)
                ldsm4(bf[bt], sB + swz((bRow + bt * 16) * 128 + (ks * 2 + bCol) * 16));
            #pragma unroll
            for (int mt = 0; mt < 2; mt++)
                #pragma unroll
                for (int bt = 0; bt < 4; bt++) {
                    mma16816(C[mt][2 * bt],     af[mt], bf[bt][0], bf[bt][1]);
                    mma16816(C[mt][2 * bt + 1], af[mt], bf[bt][2], bf[bt][3]);
                }
        }
    }

    // ---- epilogue: *d + bias -> g_y0h (fp16) ----
    int obase = ot * 128 + wm * 32;
    __half* y0n = g_y0h + (size_t)n * 512 * 4356;
    bool tail = (pt == 34);
    #pragma unroll
    for (int mt = 0; mt < 2; mt++) {
        int r0 = obase + mt * 16 + (lane >> 2);
        int r1 = r0 + 8;
        float d0 = g_d[n * 512 + r0], bb0 = cbias[r0];
        float d1 = g_d[n * 512 + r1], bb1 = cbias[r1];
        __half* row0 = y0n + (size_t)r0 * 4356;
        __half* row1 = y0n + (size_t)r1 * 4356;
        #pragma unroll
        for (int nt = 0; nt < 8; nt++) {
            int p = p0 + wn * 64 + nt * 8 + 2 * (lane & 3);
            if (!tail || p + 1 < 4356) {
                *(__half2*)(row0 + p) = __floats2half2_rn(C[mt][nt][0] * d0 + bb0, C[mt][nt][1] * d0 + bb0);
                *(__half2*)(row1 + p) = __floats2half2_rn(C[mt][nt][2] * d1 + bb1, C[mt][nt][3] * d1 + bb1);
            } else if (p < 4356) {
                row0[p] = __float2half(C[mt][nt][0] * d0 + bb0);
                row1[p] = __float2half(C[mt][nt][2] * d1 + bb1);
            }
        }
    }
}

// ---------------- K7: fused filtered_lrelu (half2 SIMD, row-pair packed) ----------------
// Region A (off 0):     SIN half[76][68] (10336B)  then  ZI half2[69][140] (38640B)
// Region B (off 38640): T1I half2[69][80] (22080B) then  VI float2[69][64] (35328B)
#define FL_B_OFF 38640
#define FL_SMEM  (FL_B_OFF + 35328)
__global__ __launch_bounds__(512) void k_flrelu(const float* __restrict__ uf,
                                                const float* __restrict__ dfl,
                                                float* __restrict__ out) {
    extern __shared__ char smc[];
    __half*  SINh = (__half*)smc;
    __half2* ZI   = (__half2*)smc;
    __half2* T1I  = (__half2*)(smc + FL_B_OFF);
    float2*  VI   = (float2*)(smc + FL_B_OFF);
    __shared__ float  ds[12];
    __shared__ __half2 fse2[6], fso2[6], dsb[12];

    int tid = threadIdx.x;
    if (tid < 12) dsb[tid] = __float2half2_rn(dfl[tid]);
    else if (tid < 24) ds[tid - 12] = dfl[tid - 12];
    else if (tid < 30) fse2[tid - 24] = __float2half2_rn(uf[2 * (tid - 24) + 1]);
    else if (tid < 36) fso2[tid - 30] = __float2half2_rn(uf[2 * (tid - 30)]);

    const __half* img = g_y0h + (size_t)blockIdx.x * (66 * 66);
    const __half hz = __float2half(0.f);

    // P0: SIN (half copy) + zero full T1I region (borders)
    for (int idx = tid; idx < 76 * 68; idx += 512) {
        int row = idx / 68, col = idx - row * 68;
        int ry = row - 5;
        __half v = hz;
        if (ry >= 0 && ry < 66 && col < 66) v = img[ry * 66 + col];
        SINh[idx] = v;
    }
    for (int idx = tid; idx < 69 * 80; idx += 512)
        ((uint32_t*)T1I)[idx] = 0u;
    __syncthreads();

    // P1: vertical up-FIR over x-pairs; T1I[m][col] = (T1[2m][col], T1[2m+1][col])
    for (int idx = tid; idx < 69 * 33; idx += 512) {
        int m = idx / 33, xp = idx - m * 33;
        __half2 se = __half2half2(hz), so = se;
        #pragma unroll
        for (int k = 0; k < 6; k++) {
            __half2 av = *(const __half2*)&SINh[(m + 1 + k) * 68 + 2 * xp];
            se = __hfma2(fse2[k], av, se);
            so = __hfma2(fso2[k], av, so);
        }
        int base = m * 80 + 2 * xp + 5;
        T1I[base]     = __lows2half2(se, so);
        T1I[base + 1] = __highs2half2(se, so);
    }
    __syncthreads();

    // P2: horizontal up-FIR + lrelu*4*sqrt2 + clamp over row-pairs -> ZI
    {
        const __half2 c02   = __float2half2_rn(0.2f);
        const __half2 cgain = __float2half2_rn(5.656854249492381f);
        const __half2 cpos  = __float2half2_rn(256.f);
        const __half2 cneg  = __float2half2_rn(-256.f);
        const __half2 zz    = __half2half2(hz);
        for (int idx = tid; idx < 69 * 69; idx += 512) {
            int r = idx / 69, m2 = idx - r * 69;
            __half2 ze = zz, zo = zz;
            #pragma unroll
            for (int k = 0; k < 6; k++) {
                __half2 tv = T1I[r * 80 + m2 + 1 + k];
                ze = __hfma2(fse2[k], tv, ze);
                zo = __hfma2(fso2[k], tv, zo);
            }
            __half2 le = __hmul2(__hfma2(__hmin2(ze, zz), c02, __hmax2(ze, zz)), cgain);
            __half2 lo = __hmul2(__hfma2(__hmin2(zo, zz), c02, __hmax2(zo, zz)), cgain);
            le = __hmin2(__hmax2(le, cneg), cpos);
            lo = __hmin2(__hmax2(lo, cneg), cpos);
            ZI[r * 140 + 2 * m2]     = le;
            ZI[r * 140 + 2 * m2 + 1] = lo;
        }
    }
    __syncthreads();

    // P3: horizontal down-FIR (half2 over row-pairs) -> VI float2
    for (int idx = tid; idx < 69 * 64; idx += 512) {
        int r = idx >> 6, ox = idx & 63;
        __half2 acc = __half2half2(hz);
        #pragma unroll
        for (int t = 0; t < 12; t++)
            acc = __hfma2(dsb[t], ZI[r * 140 + 2 * ox + t], acc);
        VI[r * 64 + ox] = __half22float2(acc);
    }
    __syncthreads();

    // P4: vertical down-FIR fp32, 4 outputs/thread via 9 float2 reads
    float* o = out + (size_t)blockIdx.x * (64 * 64);
    #pragma unroll
    for (int idx = tid; idx < 1024; idx += 512) {
        int strip = idx >> 6, ox = idx & 63;
        int oy0 = strip * 4;
        float vv[18];
        #pragma unroll
        for (int jj = 0; jj < 9; jj++) {
            float2 wv = VI[(oy0 + jj) * 64 + ox];
            vv[2 * jj] = wv.x; vv[2 * jj + 1] = wv.y;
        }
        #pragma unroll
        for (int p = 0; p < 4; p++) {
            float acc = 0.f;
            #pragma unroll
            for (int t = 0; t < 12; t++) acc += ds[t] * vv[2 * p + t];
            o[(oy0 + p) * 64 + ox] = acc;
        }
    }
}

// ---------------- launch ----------------
extern "C" void kernel_launch(void* const* d_in, const int* in_sizes, int n_in,
                              void* d_out, int out_size) {
    const float* x  = (const float*)d_in[0];
    const float* w  = (const float*)d_in[1];
    const float* aw = (const float*)d_in[2];
    const float* ab = (const float*)d_in[3];
    const float* cw = (const float*)d_in[4];
    const float* cb = (const float*)d_in[5];
    const float* uf = (const float*)d_in[6];
    const float* df = (const float*)d_in[7];
    float* out = (float*)d_out;
    (void)in_sizes; (void)n_in; (void)out_size;

    cudaFuncSetAttribute(k_conv,   cudaFuncAttributeMaxDynamicSharedMemorySize, 3 * STAGE_B);
    cudaFuncSetAttribute(k_flrelu, cudaFuncAttributeMaxDynamicSharedMemorySize, FL_SMEM);

    k_styles<<<NB, 512>>>(w, aw, ab);
    k_snorm<<<1, 256>>>();
    k_rn<<<COUT, 256>>>(cw);
    k_d<<<COUT, 128>>>();
    k_pad<<<dim3(68, NB), 512>>>(x);
    k_conv<<<dim3(35, 4, NB), 256, 3 * STAGE_B>>>(cb);
    k_flrelu<<<NB * COUT, 512, FL_SMEM>>>(uf, df, out);
}